// round 2
// baseline (speedup 1.0000x reference)
#include <cuda_runtime.h>

#define NN 50000
#define NE 800000

// ---------------- scratch (__device__ globals: no allocation allowed) ----------
__device__ float d_agg[NN * 16];      // NNConv accumulator (init = x@root_w + nn_bias)
__device__ float d_xt[NN * 16];       // x1 @ gat_w
__device__ float d_asrc[NN];
__device__ float d_adst[NN];
__device__ unsigned int d_menc[NN];   // segment-max, ordered-uint encoded
__device__ float d_z[NN];             // softmax denominator
__device__ float d_gout[NN * 16];     // GAT weighted sum
__device__ float d_ebuf[NE];          // leaky-relu attention logits

__device__ __forceinline__ unsigned enc_f(float f) {
    unsigned u = __float_as_uint(f);
    return (u & 0x80000000u) ? ~u : (u | 0x80000000u);
}
__device__ __forceinline__ float dec_f(unsigned k) {
    return __uint_as_float((k & 0x80000000u) ? (k & 0x7fffffffu) : ~k);
}
__device__ __forceinline__ float lrelu(float v) { return v > 0.f ? v : 0.2f * v; }

// ---------------- K0: agg = x @ root_w + nn_bias -------------------------------
__global__ void k0_root(const float* __restrict__ x, const float* __restrict__ rw,
                        const float* __restrict__ nb) {
    int n = blockIdx.x * blockDim.x + threadIdx.x;
    if (n >= NN) return;
    float xr[16];
#pragma unroll
    for (int i = 0; i < 16; i++) xr[i] = x[n * 16 + i];
#pragma unroll
    for (int o = 0; o < 16; o++) {
        float a = __ldg(&nb[o]);
#pragma unroll
        for (int i = 0; i < 16; i++) a = fmaf(xr[i], __ldg(&rw[i * 16 + o]), a);
        d_agg[n * 16 + o] = a;
    }
}

// ---------------- K2: fused EdgeMLP + einsum + scatter-add ---------------------
// smem layout (floats):
//   sW1 384 | sB1 128 | sW2 8192 | sB2 64 | sW3 16384 | sB3 256 |
//   sEA 512 (128x4) | sX 2048 (128x16) | sH1 128x130 | sH2 128x65 |
//   sMsg 128x16 | sSrc/sDst 128 ints each
#define K2_SMEM_FLOATS (384 + 128 + 8192 + 64 + 16384 + 256 + 512 + 2048 + 16640 + 8320 + 2048)
#define K2_SMEM_BYTES (K2_SMEM_FLOATS * 4 + 256 * 4)

__global__ void __launch_bounds__(256, 1)
k2_edge(const float* __restrict__ x, const int* __restrict__ ei,
        const float* __restrict__ ea,
        const float* __restrict__ w1, const float* __restrict__ b1,
        const float* __restrict__ w2, const float* __restrict__ b2,
        const float* __restrict__ w3, const float* __restrict__ b3) {
    extern __shared__ float sm[];
    float* sW1 = sm;
    float* sB1 = sW1 + 384;
    float* sW2 = sB1 + 128;
    float* sB2 = sW2 + 8192;
    float* sW3 = sB2 + 64;
    float* sB3 = sW3 + 16384;
    float* sEA = sB3 + 256;
    float* sX  = sEA + 512;
    float* sH1 = sX + 2048;     // row stride 130
    float* sH2 = sH1 + 16640;   // row stride 65
    float* sMsg = sH2 + 8320;   // row stride 16
    int* sSrc = (int*)(sMsg + 2048);
    int* sDst = sSrc + 128;

    int tid = threadIdx.x;
    for (int i = tid; i < 384; i += 256) sW1[i] = w1[i];
    for (int i = tid; i < 128; i += 256) sB1[i] = b1[i];
    for (int i = tid; i < 8192; i += 256) sW2[i] = w2[i];
    for (int i = tid; i < 64; i += 256) sB2[i] = b2[i];
    for (int i = tid; i < 16384; i += 256) sW3[i] = w3[i];
    for (int i = tid; i < 256; i += 256) sB3[i] = b3[i];
    __syncthreads();

    const int g = tid >> 4;    // rowgroup (8 rows each); warp owns rows [16w,16w+16)
    const int cg = tid & 15;   // colgroup

    for (int tile = blockIdx.x; tile < NE / 128; tile += gridDim.x) {
        int e0 = tile << 7;
        if (tid < 128) {
            sSrc[tid] = ei[e0 + tid];
            sDst[tid] = ei[NE + e0 + tid];
        }
        for (int i = tid; i < 384; i += 256)
            sEA[(i / 3) * 4 + (i % 3)] = ea[(size_t)e0 * 3 + i];
        __syncthreads();

        // gather x[src] rows (coalesced 64B rows)
        for (int i = tid; i < 2048; i += 256)
            sX[i] = x[(size_t)sSrc[i >> 4] * 16 + (i & 15)];

        // ---- layer 1: h1 = relu(ea @ W1 + b1), [128,128] ----
        {
            int c = tid & 127;
            int half = tid >> 7;
            float a0 = sW1[c], a1 = sW1[128 + c], a2 = sW1[256 + c], bb = sB1[c];
#pragma unroll 4
            for (int rr = 0; rr < 64; rr++) {
                int r = half * 64 + rr;
                float v = fmaf(sEA[r * 4 + 2], a2,
                          fmaf(sEA[r * 4 + 1], a1, fmaf(sEA[r * 4], a0, bb)));
                sH1[r * 130 + c] = fmaxf(v, 0.f);
            }
        }
        __syncthreads();

        // ---- layer 2: h2 = relu(h1 @ W2 + b2), [128,64], thread tile 8x4 ----
        {
            int c4 = cg * 4;
            float acc[8][4];
#pragma unroll
            for (int j = 0; j < 8; j++)
#pragma unroll
                for (int q = 0; q < 4; q++) acc[j][q] = 0.f;
#pragma unroll 4
            for (int k = 0; k < 128; k++) {
                float4 wv = *(const float4*)&sW2[k * 64 + c4];
#pragma unroll
                for (int j = 0; j < 8; j++) {
                    float a = sH1[(g * 8 + j) * 130 + k];
                    acc[j][0] = fmaf(a, wv.x, acc[j][0]);
                    acc[j][1] = fmaf(a, wv.y, acc[j][1]);
                    acc[j][2] = fmaf(a, wv.z, acc[j][2]);
                    acc[j][3] = fmaf(a, wv.w, acc[j][3]);
                }
            }
#pragma unroll
            for (int j = 0; j < 8; j++)
#pragma unroll
                for (int q = 0; q < 4; q++)
                    sH2[(g * 8 + j) * 65 + c4 + q] = fmaxf(acc[j][q] + sB2[c4 + q], 0.f);
        }
        __syncthreads();

        // ---- layer 3 + einsum:
        // msg[r][o] = sum_i x[r][i] * ( b3[i*16+o] + sum_k h2[r][k]*W3[k][i*16+o] )
        // GEMM over io in [0,256), thread tile 8 rows x 8 io-cols, 2 passes.
        // i = io/16 is constant per (pass,cg); scale by x then butterfly-reduce
        // over lane bits 1..3 (= i within pass).
#pragma unroll 1
        for (int p = 0; p < 2; p++) {
            int iobase = p * 128 + cg * 8;
            int iidx = iobase >> 4;
            float acc[8][8];
#pragma unroll
            for (int j = 0; j < 8; j++)
#pragma unroll
                for (int u = 0; u < 8; u++) acc[j][u] = 0.f;
#pragma unroll 4
            for (int k = 0; k < 64; k++) {
                const float* wr = &sW3[k * 256 + iobase];
                float4 bv0 = *(const float4*)wr;
                float4 bv1 = *(const float4*)(wr + 4);
#pragma unroll
                for (int j = 0; j < 8; j++) {
                    float a = sH2[(g * 8 + j) * 65 + k];
                    acc[j][0] = fmaf(a, bv0.x, acc[j][0]);
                    acc[j][1] = fmaf(a, bv0.y, acc[j][1]);
                    acc[j][2] = fmaf(a, bv0.z, acc[j][2]);
                    acc[j][3] = fmaf(a, bv0.w, acc[j][3]);
                    acc[j][4] = fmaf(a, bv1.x, acc[j][4]);
                    acc[j][5] = fmaf(a, bv1.y, acc[j][5]);
                    acc[j][6] = fmaf(a, bv1.z, acc[j][6]);
                    acc[j][7] = fmaf(a, bv1.w, acc[j][7]);
                }
            }
            float bb[8];
#pragma unroll
            for (int u = 0; u < 8; u++) bb[u] = sB3[iobase + u];
#pragma unroll
            for (int j = 0; j < 8; j++) {
                float xv = sX[(g * 8 + j) * 16 + iidx];
#pragma unroll
                for (int u = 0; u < 8; u++) acc[j][u] = (acc[j][u] + bb[u]) * xv;
            }
            // reduce over i (cg bits 1..3 == lane bits 1..3)
#pragma unroll
            for (int msk = 2; msk <= 8; msk <<= 1)
#pragma unroll
                for (int j = 0; j < 8; j++)
#pragma unroll
                    for (int u = 0; u < 8; u++)
                        acc[j][u] += __shfl_xor_sync(0xffffffffu, acc[j][u], msk);
            if (cg < 2) {
                int ob = cg * 8;  // cg parity selects o-range 0-7 / 8-15
#pragma unroll
                for (int j = 0; j < 8; j++)
#pragma unroll
                    for (int u = 0; u < 8; u++) {
                        int a = (g * 8 + j) * 16 + ob + u;
                        if (p == 0) sMsg[a] = acc[j][u];
                        else        sMsg[a] += acc[j][u];
                    }
            }
        }
        __syncwarp();
        // ---- flush: warp-exclusive rows -> global atomic scatter-add ----
        {
            int w = tid >> 5, lane = tid & 31;
#pragma unroll
            for (int idx = lane; idx < 256; idx += 32) {
                int r = (w << 4) + (idx >> 4);
                int o = idx & 15;
                atomicAdd(&d_agg[(size_t)sDst[r] * 16 + o], sMsg[r * 16 + o]);
            }
        }
        __syncthreads();
    }
}

// ---------------- K3: x1 = relu(agg); xt = x1@gat_w; attention scalars ---------
__global__ void k3_node(const float* __restrict__ gw, const float* __restrict__ as_,
                        const float* __restrict__ ad_) {
    __shared__ float sw[256], sa[16], sb[16];
    int tid = threadIdx.x;
    if (tid < 256) sw[tid] = gw[tid];
    if (tid < 16) { sa[tid] = as_[tid]; sb[tid] = ad_[tid]; }
    __syncthreads();
    int n = blockIdx.x * blockDim.x + tid;
    if (n >= NN) return;
    float x1[16];
#pragma unroll
    for (int i = 0; i < 16; i++) x1[i] = fmaxf(d_agg[n * 16 + i], 0.f);
    float asrc = 0.f, adst = 0.f;
#pragma unroll
    for (int o = 0; o < 16; o++) {
        float v = 0.f;
#pragma unroll
        for (int i = 0; i < 16; i++) v = fmaf(x1[i], sw[i * 16 + o], v);
        d_xt[n * 16 + o] = v;
        asrc = fmaf(v, sa[o], asrc);
        adst = fmaf(v, sb[o], adst);
    }
    d_asrc[n] = asrc;
    d_adst[n] = adst;
    d_menc[n] = enc_f(lrelu(asrc + adst));  // self-loop seeds the segment max
}

// ---------------- K4: edge logits + segment max --------------------------------
__global__ void k4_edge(const int* __restrict__ ei) {
    int e = blockIdx.x * blockDim.x + threadIdx.x;
    if (e >= NE) return;
    int s = ei[e], d = ei[NE + e];
    float v = lrelu(d_asrc[s] + d_adst[d]);
    d_ebuf[e] = v;
    atomicMax(&d_menc[d], enc_f(v));
}

// ---------------- K5: init z / gout with self-loop contribution ---------------
__global__ void k5_node() {
    int n = blockIdx.x * blockDim.x + threadIdx.x;
    if (n >= NN) return;
    float m = dec_f(d_menc[n]);
    float es = lrelu(d_asrc[n] + d_adst[n]);
    float w = expf(es - m);
    d_z[n] = w;
#pragma unroll
    for (int o = 0; o < 16; o++) d_gout[n * 16 + o] = w * d_xt[n * 16 + o];
}

// ---------------- K6: softmax-weighted scatter (16 threads / edge) ------------
__global__ void k6_edge(const int* __restrict__ ei) {
    int gid = blockIdx.x * blockDim.x + threadIdx.x;
    if (gid >= NE * 16) return;
    int e = gid >> 4, o = gid & 15;
    int s = ei[e], d = ei[NE + e];
    float m = dec_f(d_menc[d]);
    float w = expf(d_ebuf[e] - m);
    atomicAdd(&d_gout[(size_t)d * 16 + o], w * d_xt[(size_t)s * 16 + o]);
    if (o == 0) atomicAdd(&d_z[d], w);
}

// ---------------- K7: normalize, gat bias, relu, fc1, relu --------------------
__global__ void k7_node(const float* __restrict__ fw, const float* __restrict__ fb,
                        const float* __restrict__ gb, float* __restrict__ out) {
    __shared__ float sw[1024], sbv[64], sgb[16];
    int tid = threadIdx.x;
    for (int i = tid; i < 1024; i += blockDim.x) sw[i] = fw[i];
    if (tid < 64) sbv[tid] = fb[tid];
    if (tid < 16) sgb[tid] = gb[tid];
    __syncthreads();
    int n = blockIdx.x * blockDim.x + tid;
    if (n >= NN) return;
    float inv = 1.f / d_z[n];
    float x2[16];
#pragma unroll
    for (int i = 0; i < 16; i++)
        x2[i] = fmaxf(d_gout[n * 16 + i] * inv + sgb[i], 0.f);
#pragma unroll 4
    for (int j = 0; j < 64; j++) {
        float a = sbv[j];
#pragma unroll
        for (int i = 0; i < 16; i++) a = fmaf(x2[i], sw[i * 64 + j], a);
        out[(size_t)n * 64 + j] = fmaxf(a, 0.f);
    }
}

// ---------------- launch -------------------------------------------------------
extern "C" void kernel_launch(void* const* d_in, const int* in_sizes, int n_in,
                              void* d_out, int out_size) {
    const float* x      = (const float*)d_in[0];
    const int* ei       = (const int*)d_in[1];   // int32 (JAX x64 disabled)
    const float* ea     = (const float*)d_in[2];
    // d_in[3] = batch (unused)
    const float* w1     = (const float*)d_in[4];
    const float* b1     = (const float*)d_in[5];
    const float* w2     = (const float*)d_in[6];
    const float* b2     = (const float*)d_in[7];
    const float* w3     = (const float*)d_in[8];
    const float* b3     = (const float*)d_in[9];
    const float* rootw  = (const float*)d_in[10];
    const float* nnb    = (const float*)d_in[11];
    const float* gatw   = (const float*)d_in[12];
    const float* atts   = (const float*)d_in[13];
    const float* attd   = (const float*)d_in[14];
    const float* gatb   = (const float*)d_in[15];
    const float* fc1w   = (const float*)d_in[16];
    const float* fc1b   = (const float*)d_in[17];
    float* out = (float*)d_out;

    cudaFuncSetAttribute(k2_edge, cudaFuncAttributeMaxDynamicSharedMemorySize,
                         K2_SMEM_BYTES);

    const int NB = (NN + 255) / 256;
    k0_root<<<NB, 256>>>(x, rootw, nnb);
    k2_edge<<<148, 256, K2_SMEM_BYTES>>>(x, ei, ea, w1, b1, w2, b2, w3, b3);
    k3_node<<<NB, 256>>>(gatw, atts, attd);
    k4_edge<<<(NE + 255) / 256, 256>>>(ei);
    k5_node<<<NB, 256>>>();
    k6_edge<<<(NE * 16) / 256, 256>>>(ei);
    k7_node<<<NB, 256>>>(fc1w, fc1b, gatb, out);
}

// round 4
// speedup vs baseline: 2.9826x; 2.9826x over previous
#include <cuda_runtime.h>
#include <cuda_bf16.h>
#include <cstdint>

#define NN 50000
#define NE 800000
#define NTILES (NE / 128)

// ---------------- device scratch ----------------------------------------------
__device__ float d_agg[NN * 16];
__device__ float d_b3t[NN * 16];      // per-node sum_i x[i]*b3[i*16+o]
__device__ float d_xt[NN * 16];
__device__ float d_asrc[NN];
__device__ float d_adst[NN];
__device__ unsigned int d_menc[NN];
__device__ float d_z[NN];
__device__ float d_gout[NN * 16];
__device__ float d_ebuf[NE];
// packed weight images: B2P (8192 u32) | B3P (16384 u32) | w1P (512 f32) | b2 (64 f32)
__device__ unsigned d_wimg[25152];

// ---------------- helpers ------------------------------------------------------
__device__ __forceinline__ unsigned enc_f(float f) {
    unsigned u = __float_as_uint(f);
    return (u & 0x80000000u) ? ~u : (u | 0x80000000u);
}
__device__ __forceinline__ float dec_f(unsigned k) {
    return __uint_as_float((k & 0x80000000u) ? (k & 0x7fffffffu) : ~k);
}
__device__ __forceinline__ float lrelu(float v) { return v > 0.f ? v : 0.2f * v; }

// pack two f32 -> bf16x2 reg: low half = a, high half = b
__device__ __forceinline__ unsigned packbf(float a, float b) {
    unsigned r;
    asm("cvt.rn.bf16x2.f32 %0, %1, %2;" : "=r"(r) : "f"(b), "f"(a));
    return r;
}
// residual of a packed pair vs originals -> packed lo
__device__ __forceinline__ unsigned lobf(unsigned hi, float a, float b) {
    float ha = __uint_as_float(hi << 16);
    float hb = __uint_as_float(hi & 0xFFFF0000u);
    return packbf(a - ha, b - hb);
}

__device__ __forceinline__ void mma16816(float* c, const unsigned* a,
                                         unsigned b0, unsigned b1) {
    asm volatile(
        "mma.sync.aligned.m16n8k16.row.col.f32.bf16.bf16.f32 "
        "{%0,%1,%2,%3}, {%4,%5,%6,%7}, {%8,%9}, {%0,%1,%2,%3};"
        : "+f"(c[0]), "+f"(c[1]), "+f"(c[2]), "+f"(c[3])
        : "r"(a[0]), "r"(a[1]), "r"(a[2]), "r"(a[3]), "r"(b0), "r"(b1));
}

// smem byte offsets inside k2
#define SM_B2P 0
#define SM_B3P 32768
#define SM_W1P 98304
#define SM_B2B 100352
#define K2_SMEM 100608

// ---------------- K1: pack weights into fragment-order hi/lo images ------------
// B fragment (m16n8k16): b0={B[k0,n],B[k0+1,n]} k0=2*(lane%4), n=lane/4; b1: k0+8.
// Image word j: 0=b0_hi 1=b1_hi 2=b0_lo 3=b1_lo  -> one LDS.128 per (s,nt).
__global__ void k1_prep(const float* __restrict__ w1, const float* __restrict__ b1,
                        const float* __restrict__ w2, const float* __restrict__ w3,
                        const float* __restrict__ b2) {
    int t = blockIdx.x * blockDim.x + threadIdx.x;
    if (t >= 25152) return;
    if (t < 8192) {               // B2P from W2 [128,64]
        int j = t & 3, lane = (t >> 2) & 31, nt = (t >> 7) & 7, s = t >> 10;
        int kk = 16 * s + 2 * (lane & 3) + ((j & 1) ? 8 : 0);
        int n = 8 * nt + (lane >> 2);
        float va = w2[kk * 64 + n], vb = w2[(kk + 1) * 64 + n];
        unsigned hi = packbf(__bfloat162float(__float2bfloat16_rn(va)),
                             __bfloat162float(__float2bfloat16_rn(vb)));
        d_wimg[t] = (j < 2) ? hi : lobf(hi, va, vb);
    } else if (t < 24576) {       // B3P from W3 [64,256]
        int u = t - 8192;
        int j = u & 3, lane = (u >> 2) & 31, nt = (u >> 7) & 31, s3 = u >> 12;
        int kk = 16 * s3 + 2 * (lane & 3) + ((j & 1) ? 8 : 0);
        int n = 8 * nt + (lane >> 2);
        float va = w3[kk * 256 + n], vb = w3[(kk + 1) * 256 + n];
        unsigned hi = packbf(__bfloat162float(__float2bfloat16_rn(va)),
                             __bfloat162float(__float2bfloat16_rn(vb)));
        d_wimg[t] = (j < 2) ? hi : lobf(hi, va, vb);
    } else if (t < 25088) {       // w1P: [s][q][j][4] = {w1[0,c],w1[1,c],w1[2,c],b1[c]}
        int f = t - 24576;
        int comp = f & 3, j = (f >> 2) & 3, q = (f >> 4) & 3, s = f >> 6;
        int c = 16 * s + 2 * q + (j & 1) + (j >> 1) * 8;
        float v = (comp < 3) ? w1[comp * 128 + c] : b1[c];
        d_wimg[t] = __float_as_uint(v);
    } else {                      // b2
        d_wimg[t] = __float_as_uint(b2[t - 25088]);
    }
}

// ---------------- K0: agg init + b3 term ---------------------------------------
__global__ void k0_root(const float* __restrict__ x, const float* __restrict__ rw,
                        const float* __restrict__ nb, const float* __restrict__ b3) {
    int n = blockIdx.x * blockDim.x + threadIdx.x;
    if (n >= NN) return;
    float xr[16];
#pragma unroll
    for (int i = 0; i < 16; i++) xr[i] = x[n * 16 + i];
#pragma unroll
    for (int o = 0; o < 16; o++) {
        float a = __ldg(&nb[o]);
        float b = 0.f;
#pragma unroll
        for (int i = 0; i < 16; i++) {
            a = fmaf(xr[i], __ldg(&rw[i * 16 + o]), a);
            b = fmaf(xr[i], __ldg(&b3[i * 16 + o]), b);
        }
        d_agg[n * 16 + o] = a;
        d_b3t[n * 16 + o] = b;
    }
}

// ---------------- K2: fused edge pipeline on mma.sync bf16 (3-term split) ------
__global__ void __launch_bounds__(256, 2)
k2_edge(const float* __restrict__ x, const int* __restrict__ ei,
        const float* __restrict__ ea) {
    extern __shared__ unsigned char smc[];
    int tid = threadIdx.x;
    // copy packed weight images (100608 B = 6288 uint4)
    {
        const uint4* src = (const uint4*)d_wimg;
        uint4* dst = (uint4*)smc;
        for (int i = tid; i < 6288; i += 256) dst[i] = src[i];
    }
    __syncthreads();

    const int w = tid >> 5, lane = tid & 31;
    const int q = lane & 3, l4 = lane >> 2;
    const int bq = 2 * q;                 // fragment col base
    const float* sw1 = (const float*)(smc + SM_W1P);
    const float* sb2 = (const float*)(smc + SM_B2B);

    for (int tile = blockIdx.x; tile < NTILES; tile += gridDim.x) {
        const int e0 = tile << 7;
        const int r0g = 16 * w + l4;      // tile-local edge rows for this thread
        const int er0 = e0 + r0g, er1 = er0 + 8;
        const int src0 = __ldg(&ei[er0]), src1 = __ldg(&ei[er1]);
        const int dst0 = __ldg(&ei[NE + er0]), dst1 = __ldg(&ei[NE + er1]);
        // edge attrs for both rows
        const float ea00 = __ldg(&ea[(size_t)er0 * 3]);
        const float ea01 = __ldg(&ea[(size_t)er0 * 3 + 1]);
        const float ea02 = __ldg(&ea[(size_t)er0 * 3 + 2]);
        const float ea10 = __ldg(&ea[(size_t)er1 * 3]);
        const float ea11 = __ldg(&ea[(size_t)er1 * 3 + 1]);
        const float ea12 = __ldg(&ea[(size_t)er1 * 3 + 2]);
        // x[src] quarters (lane q owns cols 4q..4q+3; shared via shfl later)
        const float4 xq0 = *(const float4*)&x[(size_t)src0 * 16 + 4 * q];
        const float4 xq1 = *(const float4*)&x[(size_t)src1 * 16 + 4 * q];

        // ---- L2 (with fused L1): C2[16,64] per warp ----
        float C2[8][4];
#pragma unroll
        for (int nt = 0; nt < 8; nt++)
#pragma unroll
            for (int v = 0; v < 4; v++) C2[nt][v] = 0.f;

#pragma unroll
        for (int s = 0; s < 8; s++) {
            float h0[4], h1[4];
#pragma unroll
            for (int j = 0; j < 4; j++) {
                float4 wf = *(const float4*)&sw1[(((s * 4 + q) * 4) + j) * 4];
                h0[j] = fmaxf(fmaf(ea02, wf.z, fmaf(ea01, wf.y, fmaf(ea00, wf.x, wf.w))), 0.f);
                h1[j] = fmaxf(fmaf(ea12, wf.z, fmaf(ea11, wf.y, fmaf(ea10, wf.x, wf.w))), 0.f);
            }
            unsigned Ah[4], Al[4];
            Ah[0] = packbf(h0[0], h0[1]); Al[0] = lobf(Ah[0], h0[0], h0[1]);
            Ah[1] = packbf(h1[0], h1[1]); Al[1] = lobf(Ah[1], h1[0], h1[1]);
            Ah[2] = packbf(h0[2], h0[3]); Al[2] = lobf(Ah[2], h0[2], h0[3]);
            Ah[3] = packbf(h1[2], h1[3]); Al[3] = lobf(Ah[3], h1[2], h1[3]);
#pragma unroll
            for (int nt = 0; nt < 8; nt++) {
                uint4 B = *(const uint4*)(smc + SM_B2P + (((s * 8 + nt) * 32 + lane) << 4));
                mma16816(C2[nt], Ah, B.x, B.y);
                mma16816(C2[nt], Al, B.x, B.y);
                mma16816(C2[nt], Ah, B.z, B.w);
            }
        }

        // ---- epilogue: +b2, relu, split -> A3 fragments (no smem roundtrip) ----
        unsigned A3h[4][4], A3l[4][4];
#pragma unroll
        for (int s3 = 0; s3 < 4; s3++) {
            int c = 16 * s3 + bq;
            float2 bA = *(const float2*)&sb2[c];
            float2 bB = *(const float2*)&sb2[c + 8];
            float v00 = fmaxf(C2[2 * s3][0] + bA.x, 0.f);
            float v01 = fmaxf(C2[2 * s3][1] + bA.y, 0.f);
            float v10 = fmaxf(C2[2 * s3][2] + bA.x, 0.f);
            float v11 = fmaxf(C2[2 * s3][3] + bA.y, 0.f);
            float v20 = fmaxf(C2[2 * s3 + 1][0] + bB.x, 0.f);
            float v21 = fmaxf(C2[2 * s3 + 1][1] + bB.y, 0.f);
            float v30 = fmaxf(C2[2 * s3 + 1][2] + bB.x, 0.f);
            float v31 = fmaxf(C2[2 * s3 + 1][3] + bB.y, 0.f);
            A3h[s3][0] = packbf(v00, v01); A3l[s3][0] = lobf(A3h[s3][0], v00, v01);
            A3h[s3][1] = packbf(v10, v11); A3l[s3][1] = lobf(A3h[s3][1], v10, v11);
            A3h[s3][2] = packbf(v20, v21); A3l[s3][2] = lobf(A3h[s3][2], v20, v21);
            A3h[s3][3] = packbf(v30, v31); A3l[s3][3] = lobf(A3h[s3][3], v30, v31);
        }

        // ---- L3 + einsum: msg[r,o] = sum_i x[r,i]*C3[r,16i+o] ----
        float macc[2][4];
#pragma unroll
        for (int r = 0; r < 2; r++)
#pragma unroll
            for (int jj = 0; jj < 4; jj++) macc[r][jj] = 0.f;

#pragma unroll
        for (int grp = 0; grp < 8; grp++) {
            float C3[4][4];
#pragma unroll
            for (int t = 0; t < 4; t++)
#pragma unroll
                for (int v = 0; v < 4; v++) C3[t][v] = 0.f;
#pragma unroll
            for (int s3 = 0; s3 < 4; s3++) {
#pragma unroll
                for (int t = 0; t < 4; t++) {
                    int nt = grp * 4 + t;
                    uint4 B = *(const uint4*)(smc + SM_B3P + (((s3 * 32 + nt) * 32 + lane) << 4));
                    mma16816(C3[t], A3h[s3], B.x, B.y);
                    mma16816(C3[t], A3l[s3], B.x, B.y);
                    mma16816(C3[t], A3h[s3], B.z, B.w);
                }
            }
#pragma unroll
            for (int t = 0; t < 4; t++) {
                const int nt = grp * 4 + t;
                const int i = nt >> 1;               // compile-time (full unroll)
                const int sl = (lane & ~3) | (i >> 2);
                float own0, own1;
                switch (i & 3) {                     // compile-time component
                    case 0: own0 = xq0.x; own1 = xq1.x; break;
                    case 1: own0 = xq0.y; own1 = xq1.y; break;
                    case 2: own0 = xq0.z; own1 = xq1.z; break;
                    default: own0 = xq0.w; own1 = xq1.w; break;
                }
                float xv0 = __shfl_sync(0xffffffffu, own0, sl);
                float xv1 = __shfl_sync(0xffffffffu, own1, sl);
                const int p = nt & 1;
                macc[0][2 * p]     = fmaf(C3[t][0], xv0, macc[0][2 * p]);
                macc[0][2 * p + 1] = fmaf(C3[t][1], xv0, macc[0][2 * p + 1]);
                macc[1][2 * p]     = fmaf(C3[t][2], xv1, macc[1][2 * p]);
                macc[1][2 * p + 1] = fmaf(C3[t][3], xv1, macc[1][2 * p + 1]);
            }
        }

        // ---- flush: + b3t[src], atomic into d_agg[dst] ----
        {
            float2 p00 = *(const float2*)&d_b3t[(size_t)src0 * 16 + bq];
            float2 p01 = *(const float2*)&d_b3t[(size_t)src0 * 16 + bq + 8];
            float2 p10 = *(const float2*)&d_b3t[(size_t)src1 * 16 + bq];
            float2 p11 = *(const float2*)&d_b3t[(size_t)src1 * 16 + bq + 8];
            float* a0 = &d_agg[(size_t)dst0 * 16];
            float* a1 = &d_agg[(size_t)dst1 * 16];
            atomicAdd(a0 + bq,     macc[0][0] + p00.x);
            atomicAdd(a0 + bq + 1, macc[0][1] + p00.y);
            atomicAdd(a0 + bq + 8, macc[0][2] + p01.x);
            atomicAdd(a0 + bq + 9, macc[0][3] + p01.y);
            atomicAdd(a1 + bq,     macc[1][0] + p10.x);
            atomicAdd(a1 + bq + 1, macc[1][1] + p10.y);
            atomicAdd(a1 + bq + 8, macc[1][2] + p11.x);
            atomicAdd(a1 + bq + 9, macc[1][3] + p11.y);
        }
    }
}

// ---------------- K3: x1 = relu(agg); xt = x1@gat_w; attention scalars ---------
__global__ void k3_node(const float* __restrict__ gw, const float* __restrict__ as_,
                        const float* __restrict__ ad_) {
    __shared__ float sw[256], sa[16], sbv[16];
    int tid = threadIdx.x;
    if (tid < 256) sw[tid] = gw[tid];
    if (tid < 16) { sa[tid] = as_[tid]; sbv[tid] = ad_[tid]; }
    __syncthreads();
    int n = blockIdx.x * blockDim.x + tid;
    if (n >= NN) return;
    float x1[16];
#pragma unroll
    for (int i = 0; i < 16; i++) x1[i] = fmaxf(d_agg[n * 16 + i], 0.f);
    float asrc = 0.f, adst = 0.f;
#pragma unroll
    for (int o = 0; o < 16; o++) {
        float v = 0.f;
#pragma unroll
        for (int i = 0; i < 16; i++) v = fmaf(x1[i], sw[i * 16 + o], v);
        d_xt[n * 16 + o] = v;
        asrc = fmaf(v, sa[o], asrc);
        adst = fmaf(v, sbv[o], adst);
    }
    d_asrc[n] = asrc;
    d_adst[n] = adst;
    d_menc[n] = enc_f(lrelu(asrc + adst));   // self-loop seeds the max
}

// ---------------- K4: edge logits + segment max --------------------------------
__global__ void k4_edge(const int* __restrict__ ei) {
    int e = blockIdx.x * blockDim.x + threadIdx.x;
    if (e >= NE) return;
    int s = ei[e], d = ei[NE + e];
    float v = lrelu(d_asrc[s] + d_adst[d]);
    d_ebuf[e] = v;
    atomicMax(&d_menc[d], enc_f(v));
}

// ---------------- K5: init z / gout with self-loop -----------------------------
__global__ void k5_node() {
    int n = blockIdx.x * blockDim.x + threadIdx.x;
    if (n >= NN) return;
    float m = dec_f(d_menc[n]);
    float es = lrelu(d_asrc[n] + d_adst[n]);
    float wv = expf(es - m);
    d_z[n] = wv;
#pragma unroll
    for (int o = 0; o < 16; o++) d_gout[n * 16 + o] = wv * d_xt[n * 16 + o];
}

// ---------------- K6: softmax-weighted scatter ---------------------------------
__global__ void k6_edge(const int* __restrict__ ei) {
    int gid = blockIdx.x * blockDim.x + threadIdx.x;
    if (gid >= NE * 16) return;
    int e = gid >> 4, o = gid & 15;
    int s = ei[e], d = ei[NE + e];
    float m = dec_f(d_menc[d]);
    float wv = expf(d_ebuf[e] - m);
    atomicAdd(&d_gout[(size_t)d * 16 + o], wv * d_xt[(size_t)s * 16 + o]);
    if (o == 0) atomicAdd(&d_z[d], wv);
}

// ---------------- K7: normalize, gat bias, relu, fc1, relu ---------------------
__global__ void k7_node(const float* __restrict__ fw, const float* __restrict__ fb,
                        const float* __restrict__ gb, float* __restrict__ out) {
    __shared__ float sw[1024], sbv[64], sgb[16];
    int tid = threadIdx.x;
    for (int i = tid; i < 1024; i += blockDim.x) sw[i] = fw[i];
    if (tid < 64) sbv[tid] = fb[tid];
    if (tid < 16) sgb[tid] = gb[tid];
    __syncthreads();
    int n = blockIdx.x * blockDim.x + tid;
    if (n >= NN) return;
    float inv = 1.f / d_z[n];
    float x2[16];
#pragma unroll
    for (int i = 0; i < 16; i++)
        x2[i] = fmaxf(d_gout[n * 16 + i] * inv + sgb[i], 0.f);
#pragma unroll 4
    for (int j = 0; j < 64; j++) {
        float a = sbv[j];
#pragma unroll
        for (int i = 0; i < 16; i++) a = fmaf(x2[i], sw[i * 64 + j], a);
        out[(size_t)n * 64 + j] = fmaxf(a, 0.f);
    }
}

// ---------------- launch -------------------------------------------------------
extern "C" void kernel_launch(void* const* d_in, const int* in_sizes, int n_in,
                              void* d_out, int out_size) {
    const float* x = (const float*)d_in[0];
    const int* ei = (const int*)d_in[1];
    const float* ea = (const float*)d_in[2];
    const float* w1 = (const float*)d_in[4];
    const float* b1 = (const float*)d_in[5];
    const float* w2 = (const float*)d_in[6];
    const float* b2 = (const float*)d_in[7];
    const float* w3 = (const float*)d_in[8];
    const float* b3 = (const float*)d_in[9];
    const float* rootw = (const float*)d_in[10];
    const float* nnb = (const float*)d_in[11];
    const float* gatw = (const float*)d_in[12];
    const float* atts = (const float*)d_in[13];
    const float* attd = (const float*)d_in[14];
    const float* gatb = (const float*)d_in[15];
    const float* fc1w = (const float*)d_in[16];
    const float* fc1b = (const float*)d_in[17];
    float* out = (float*)d_out;

    cudaFuncSetAttribute(k2_edge, cudaFuncAttributeMaxDynamicSharedMemorySize, K2_SMEM);

    const int NB = (NN + 255) / 256;
    k1_prep<<<(25152 + 255) / 256, 256>>>(w1, b1, w2, w3, b2);
    k0_root<<<NB, 256>>>(x, rootw, nnb, b3);
    k2_edge<<<296, 256, K2_SMEM>>>(x, ei, ea);
    k3_node<<<NB, 256>>>(gatw, atts, attd);
    k4_edge<<<(NE + 255) / 256, 256>>>(ei);
    k5_node<<<NB, 256>>>();
    k6_edge<<<(NE * 16) / 256, 256>>>(ei);
    k7_node<<<NB, 256>>>(fc1w, fc1b, gatb, out);
}

// round 5
// speedup vs baseline: 3.3922x; 1.1373x over previous
#include <cuda_runtime.h>
#include <cuda_fp16.h>
#include <cstdint>

#define NN 50000
#define NE 800000
#define NTILES (NE / 128)

// ---------------- device scratch ----------------------------------------------
__device__ float d_agg[NN * 16];
__device__ float d_b3t[NN * 16];      // per-node sum_i x[i]*b3[i*16+o]
__device__ float d_xt[NN * 16];
__device__ float d_asrc[NN];
__device__ float d_adst[NN];
__device__ unsigned int d_menc[NN];
__device__ float d_z[NN];
__device__ float d_gout[NN * 16];
__device__ float d_ebuf[NE];
// packed weight images: B2P (8192 u32) | B3P (16384 u32) | w1P (512 f32) | b2 (64 f32)
__device__ unsigned d_wimg[25152];

// ---------------- helpers ------------------------------------------------------
__device__ __forceinline__ unsigned enc_f(float f) {
    unsigned u = __float_as_uint(f);
    return (u & 0x80000000u) ? ~u : (u | 0x80000000u);
}
__device__ __forceinline__ float dec_f(unsigned k) {
    return __uint_as_float((k & 0x80000000u) ? (k & 0x7fffffffu) : ~k);
}
__device__ __forceinline__ float lrelu(float v) { return v > 0.f ? v : 0.2f * v; }

// pack two f32 -> f16x2 reg: low half = a, high half = b
__device__ __forceinline__ unsigned packh(float a, float b) {
    unsigned r;
    asm("cvt.rn.f16x2.f32 %0, %1, %2;" : "=r"(r) : "f"(b), "f"(a));
    return r;
}
// residual of a packed f16 pair vs originals -> packed lo (prep only)
__device__ __forceinline__ unsigned loh(unsigned hi, float a, float b) {
    float ha = __half2float(__ushort_as_half((unsigned short)(hi & 0xFFFFu)));
    float hb = __half2float(__ushort_as_half((unsigned short)(hi >> 16)));
    return packh(a - ha, b - hb);
}

__device__ __forceinline__ void mma16816(float* c, const unsigned* a,
                                         unsigned b0, unsigned b1) {
    asm volatile(
        "mma.sync.aligned.m16n8k16.row.col.f32.f16.f16.f32 "
        "{%0,%1,%2,%3}, {%4,%5,%6,%7}, {%8,%9}, {%0,%1,%2,%3};"
        : "+f"(c[0]), "+f"(c[1]), "+f"(c[2]), "+f"(c[3])
        : "r"(a[0]), "r"(a[1]), "r"(a[2]), "r"(a[3]), "r"(b0), "r"(b1));
}

// smem byte offsets inside k2
#define SM_B2P 0
#define SM_B3P 32768
#define SM_W1P 98304
#define SM_B2B 100352
#define K2_SMEM 100608

// ---------------- K1: pack weights into fragment-order hi/lo fp16 images -------
// B fragment (m16n8k16): b0={B[k0,n],B[k0+1,n]} k0=2*(lane%4), n=lane/4; b1: k0+8.
// Image word j: 0=b0_hi 1=b1_hi 2=b0_lo 3=b1_lo  -> one LDS.128 per (s,nt).
// hi+lo is an EXACT 2-term fp16 split of the fp32 weight (error ~2^-22).
__global__ void k1_prep(const float* __restrict__ w1, const float* __restrict__ b1,
                        const float* __restrict__ w2, const float* __restrict__ w3,
                        const float* __restrict__ b2) {
    int t = blockIdx.x * blockDim.x + threadIdx.x;
    if (t >= 25152) return;
    if (t < 8192) {               // B2P from W2 [128,64]
        int j = t & 3, lane = (t >> 2) & 31, nt = (t >> 7) & 7, s = t >> 10;
        int kk = 16 * s + 2 * (lane & 3) + ((j & 1) ? 8 : 0);
        int n = 8 * nt + (lane >> 2);
        float va = w2[kk * 64 + n], vb = w2[(kk + 1) * 64 + n];
        unsigned hi = packh(va, vb);
        d_wimg[t] = (j < 2) ? hi : loh(hi, va, vb);
    } else if (t < 24576) {       // B3P from W3 [64,256]
        int u = t - 8192;
        int j = u & 3, lane = (u >> 2) & 31, nt = (u >> 7) & 31, s3 = u >> 12;
        int kk = 16 * s3 + 2 * (lane & 3) + ((j & 1) ? 8 : 0);
        int n = 8 * nt + (lane >> 2);
        float va = w3[kk * 256 + n], vb = w3[(kk + 1) * 256 + n];
        unsigned hi = packh(va, vb);
        d_wimg[t] = (j < 2) ? hi : loh(hi, va, vb);
    } else if (t < 25088) {       // w1P: [s][q][j][4] = {w1[0,c],w1[1,c],w1[2,c],b1[c]}
        int f = t - 24576;
        int comp = f & 3, j = (f >> 2) & 3, q = (f >> 4) & 3, s = f >> 6;
        int c = 16 * s + 2 * q + (j & 1) + (j >> 1) * 8;
        float v = (comp < 3) ? w1[comp * 128 + c] : b1[c];
        d_wimg[t] = __float_as_uint(v);
    } else {                      // b2
        d_wimg[t] = __float_as_uint(b2[t - 25088]);
    }
}

// ---------------- K0: agg init + b3 term ---------------------------------------
__global__ void k0_root(const float* __restrict__ x, const float* __restrict__ rw,
                        const float* __restrict__ nb, const float* __restrict__ b3) {
    int n = blockIdx.x * blockDim.x + threadIdx.x;
    if (n >= NN) return;
    float xr[16];
#pragma unroll
    for (int i = 0; i < 16; i++) xr[i] = x[n * 16 + i];
#pragma unroll
    for (int o = 0; o < 16; o++) {
        float a = __ldg(&nb[o]);
        float b = 0.f;
#pragma unroll
        for (int i = 0; i < 16; i++) {
            a = fmaf(xr[i], __ldg(&rw[i * 16 + o]), a);
            b = fmaf(xr[i], __ldg(&b3[i * 16 + o]), b);
        }
        d_agg[n * 16 + o] = a;
        d_b3t[n * 16 + o] = b;
    }
}

// ---------------- K2: fused edge pipeline, fp16 2-term (exact-B) mma.sync ------
__global__ void __launch_bounds__(256, 2)
k2_edge(const float* __restrict__ x, const int* __restrict__ ei,
        const float* __restrict__ ea) {
    extern __shared__ unsigned char smc[];
    int tid = threadIdx.x;
    // copy packed weight images (100608 B = 6288 uint4)
    {
        const uint4* src = (const uint4*)d_wimg;
        uint4* dst = (uint4*)smc;
        for (int i = tid; i < 6288; i += 256) dst[i] = src[i];
    }
    __syncthreads();

    const int w = tid >> 5, lane = tid & 31;
    const int q = lane & 3, l4 = lane >> 2;
    const int bq = 2 * q;                 // fragment col base
    const float* sw1 = (const float*)(smc + SM_W1P);
    const float* sb2 = (const float*)(smc + SM_B2B);

    for (int tile = blockIdx.x; tile < NTILES; tile += gridDim.x) {
        const int e0 = tile << 7;
        const int r0g = 16 * w + l4;      // tile-local edge rows for this thread
        const int er0 = e0 + r0g, er1 = er0 + 8;
        const int src0 = __ldg(&ei[er0]), src1 = __ldg(&ei[er1]);
        const int dst0 = __ldg(&ei[NE + er0]), dst1 = __ldg(&ei[NE + er1]);
        // edge attrs for both rows
        const float ea00 = __ldg(&ea[(size_t)er0 * 3]);
        const float ea01 = __ldg(&ea[(size_t)er0 * 3 + 1]);
        const float ea02 = __ldg(&ea[(size_t)er0 * 3 + 2]);
        const float ea10 = __ldg(&ea[(size_t)er1 * 3]);
        const float ea11 = __ldg(&ea[(size_t)er1 * 3 + 1]);
        const float ea12 = __ldg(&ea[(size_t)er1 * 3 + 2]);
        // x[src] quarters (lane q owns cols 4q..4q+3; shared via shfl later)
        const float4 xq0 = *(const float4*)&x[(size_t)src0 * 16 + 4 * q];
        const float4 xq1 = *(const float4*)&x[(size_t)src1 * 16 + 4 * q];

        // ---- L2 (with fused L1): C2[16,64] per warp ----
        float C2[8][4];
#pragma unroll
        for (int nt = 0; nt < 8; nt++)
#pragma unroll
            for (int v = 0; v < 4; v++) C2[nt][v] = 0.f;

#pragma unroll
        for (int s = 0; s < 8; s++) {
            float h0[4], h1[4];
#pragma unroll
            for (int j = 0; j < 4; j++) {
                float4 wf = *(const float4*)&sw1[(((s * 4 + q) * 4) + j) * 4];
                h0[j] = fmaxf(fmaf(ea02, wf.z, fmaf(ea01, wf.y, fmaf(ea00, wf.x, wf.w))), 0.f);
                h1[j] = fmaxf(fmaf(ea12, wf.z, fmaf(ea11, wf.y, fmaf(ea10, wf.x, wf.w))), 0.f);
            }
            unsigned Ah[4];
            Ah[0] = packh(h0[0], h0[1]);
            Ah[1] = packh(h1[0], h1[1]);
            Ah[2] = packh(h0[2], h0[3]);
            Ah[3] = packh(h1[2], h1[3]);
#pragma unroll
            for (int nt = 0; nt < 8; nt++) {
                uint4 B = *(const uint4*)(smc + SM_B2P + (((s * 8 + nt) * 32 + lane) << 4));
                mma16816(C2[nt], Ah, B.x, B.y);   // A * B_hi
                mma16816(C2[nt], Ah, B.z, B.w);   // A * B_lo
            }
        }

        // ---- epilogue: +b2, relu -> A3 fragments (no smem roundtrip) ----
        unsigned A3h[4][4];
#pragma unroll
        for (int s3 = 0; s3 < 4; s3++) {
            int c = 16 * s3 + bq;
            float2 bA = *(const float2*)&sb2[c];
            float2 bB = *(const float2*)&sb2[c + 8];
            float v00 = fmaxf(C2[2 * s3][0] + bA.x, 0.f);
            float v01 = fmaxf(C2[2 * s3][1] + bA.y, 0.f);
            float v10 = fmaxf(C2[2 * s3][2] + bA.x, 0.f);
            float v11 = fmaxf(C2[2 * s3][3] + bA.y, 0.f);
            float v20 = fmaxf(C2[2 * s3 + 1][0] + bB.x, 0.f);
            float v21 = fmaxf(C2[2 * s3 + 1][1] + bB.y, 0.f);
            float v30 = fmaxf(C2[2 * s3 + 1][2] + bB.x, 0.f);
            float v31 = fmaxf(C2[2 * s3 + 1][3] + bB.y, 0.f);
            A3h[s3][0] = packh(v00, v01);
            A3h[s3][1] = packh(v10, v11);
            A3h[s3][2] = packh(v20, v21);
            A3h[s3][3] = packh(v30, v31);
        }

        // ---- L3 + einsum: msg[r,o] = sum_i x[r,i]*C3[r,16i+o] ----
        float macc[2][4];
#pragma unroll
        for (int r = 0; r < 2; r++)
#pragma unroll
            for (int jj = 0; jj < 4; jj++) macc[r][jj] = 0.f;

#pragma unroll
        for (int grp = 0; grp < 8; grp++) {
            float C3[4][4];
#pragma unroll
            for (int t = 0; t < 4; t++)
#pragma unroll
                for (int v = 0; v < 4; v++) C3[t][v] = 0.f;
#pragma unroll
            for (int s3 = 0; s3 < 4; s3++) {
#pragma unroll
                for (int t = 0; t < 4; t++) {
                    int nt = grp * 4 + t;
                    uint4 B = *(const uint4*)(smc + SM_B3P + (((s3 * 32 + nt) * 32 + lane) << 4));
                    mma16816(C3[t], A3h[s3], B.x, B.y);   // A * B_hi
                    mma16816(C3[t], A3h[s3], B.z, B.w);   // A * B_lo
                }
            }
#pragma unroll
            for (int t = 0; t < 4; t++) {
                const int nt = grp * 4 + t;
                const int i = nt >> 1;               // compile-time (full unroll)
                const int sl = (lane & ~3) | (i >> 2);
                float own0, own1;
                switch (i & 3) {                     // compile-time component
                    case 0: own0 = xq0.x; own1 = xq1.x; break;
                    case 1: own0 = xq0.y; own1 = xq1.y; break;
                    case 2: own0 = xq0.z; own1 = xq1.z; break;
                    default: own0 = xq0.w; own1 = xq1.w; break;
                }
                float xv0 = __shfl_sync(0xffffffffu, own0, sl);
                float xv1 = __shfl_sync(0xffffffffu, own1, sl);
                const int p = nt & 1;
                macc[0][2 * p]     = fmaf(C3[t][0], xv0, macc[0][2 * p]);
                macc[0][2 * p + 1] = fmaf(C3[t][1], xv0, macc[0][2 * p + 1]);
                macc[1][2 * p]     = fmaf(C3[t][2], xv1, macc[1][2 * p]);
                macc[1][2 * p + 1] = fmaf(C3[t][3], xv1, macc[1][2 * p + 1]);
            }
        }

        // ---- flush: + b3t[src], atomic into d_agg[dst] ----
        {
            float2 p00 = *(const float2*)&d_b3t[(size_t)src0 * 16 + bq];
            float2 p01 = *(const float2*)&d_b3t[(size_t)src0 * 16 + bq + 8];
            float2 p10 = *(const float2*)&d_b3t[(size_t)src1 * 16 + bq];
            float2 p11 = *(const float2*)&d_b3t[(size_t)src1 * 16 + bq + 8];
            float* a0 = &d_agg[(size_t)dst0 * 16];
            float* a1 = &d_agg[(size_t)dst1 * 16];
            atomicAdd(a0 + bq,     macc[0][0] + p00.x);
            atomicAdd(a0 + bq + 1, macc[0][1] + p00.y);
            atomicAdd(a0 + bq + 8, macc[0][2] + p01.x);
            atomicAdd(a0 + bq + 9, macc[0][3] + p01.y);
            atomicAdd(a1 + bq,     macc[1][0] + p10.x);
            atomicAdd(a1 + bq + 1, macc[1][1] + p10.y);
            atomicAdd(a1 + bq + 8, macc[1][2] + p11.x);
            atomicAdd(a1 + bq + 9, macc[1][3] + p11.y);
        }
    }
}

// ---------------- K3: x1 = relu(agg); xt = x1@gat_w; attention scalars ---------
__global__ void k3_node(const float* __restrict__ gw, const float* __restrict__ as_,
                        const float* __restrict__ ad_) {
    __shared__ float sw[256], sa[16], sbv[16];
    int tid = threadIdx.x;
    if (tid < 256) sw[tid] = gw[tid];
    if (tid < 16) { sa[tid] = as_[tid]; sbv[tid] = ad_[tid]; }
    __syncthreads();
    int n = blockIdx.x * blockDim.x + tid;
    if (n >= NN) return;
    float x1[16];
#pragma unroll
    for (int i = 0; i < 16; i++) x1[i] = fmaxf(d_agg[n * 16 + i], 0.f);
    float asrc = 0.f, adst = 0.f;
#pragma unroll
    for (int o = 0; o < 16; o++) {
        float v = 0.f;
#pragma unroll
        for (int i = 0; i < 16; i++) v = fmaf(x1[i], sw[i * 16 + o], v);
        d_xt[n * 16 + o] = v;
        asrc = fmaf(v, sa[o], asrc);
        adst = fmaf(v, sbv[o], adst);
    }
    d_asrc[n] = asrc;
    d_adst[n] = adst;
    d_menc[n] = enc_f(lrelu(asrc + adst));   // self-loop seeds the max
}

// ---------------- K4: edge logits + segment max --------------------------------
__global__ void k4_edge(const int* __restrict__ ei) {
    int e = blockIdx.x * blockDim.x + threadIdx.x;
    if (e >= NE) return;
    int s = ei[e], d = ei[NE + e];
    float v = lrelu(d_asrc[s] + d_adst[d]);
    d_ebuf[e] = v;
    atomicMax(&d_menc[d], enc_f(v));
}

// ---------------- K5: init z / gout with self-loop -----------------------------
__global__ void k5_node() {
    int n = blockIdx.x * blockDim.x + threadIdx.x;
    if (n >= NN) return;
    float m = dec_f(d_menc[n]);
    float es = lrelu(d_asrc[n] + d_adst[n]);
    float wv = __expf(es - m);
    d_z[n] = wv;
#pragma unroll
    for (int o = 0; o < 16; o++) d_gout[n * 16 + o] = wv * d_xt[n * 16 + o];
}

// ---------------- K6: softmax-weighted scatter (4 threads / edge) --------------
__global__ void k6_edge(const int* __restrict__ ei) {
    int gid = blockIdx.x * blockDim.x + threadIdx.x;
    if (gid >= NE * 4) return;
    int e = gid >> 2, part = gid & 3;
    int s = ei[e], d = ei[NE + e];
    float wv = __expf(d_ebuf[e] - dec_f(d_menc[d]));
    float4 xv = *(const float4*)&d_xt[(size_t)s * 16 + part * 4];
    float* gp = &d_gout[(size_t)d * 16 + part * 4];
    atomicAdd(gp,     wv * xv.x);
    atomicAdd(gp + 1, wv * xv.y);
    atomicAdd(gp + 2, wv * xv.z);
    atomicAdd(gp + 3, wv * xv.w);
    if (part == 0) atomicAdd(&d_z[d], wv);
}

// ---------------- K7: normalize, gat bias, relu, fc1, relu ---------------------
__global__ void k7_node(const float* __restrict__ fw, const float* __restrict__ fb,
                        const float* __restrict__ gb, float* __restrict__ out) {
    __shared__ float sw[1024], sbv[64], sgb[16];
    int tid = threadIdx.x;
    for (int i = tid; i < 1024; i += blockDim.x) sw[i] = fw[i];
    if (tid < 64) sbv[tid] = fb[tid];
    if (tid < 16) sgb[tid] = gb[tid];
    __syncthreads();
    int n = blockIdx.x * blockDim.x + tid;
    if (n >= NN) return;
    float inv = 1.f / d_z[n];
    float x2[16];
#pragma unroll
    for (int i = 0; i < 16; i++)
        x2[i] = fmaxf(d_gout[n * 16 + i] * inv + sgb[i], 0.f);
#pragma unroll 4
    for (int j = 0; j < 64; j++) {
        float a = sbv[j];
#pragma unroll
        for (int i = 0; i < 16; i++) a = fmaf(x2[i], sw[i * 64 + j], a);
        out[(size_t)n * 64 + j] = fmaxf(a, 0.f);
    }
}

// ---------------- launch -------------------------------------------------------
extern "C" void kernel_launch(void* const* d_in, const int* in_sizes, int n_in,
                              void* d_out, int out_size) {
    const float* x = (const float*)d_in[0];
    const int* ei = (const int*)d_in[1];
    const float* ea = (const float*)d_in[2];
    const float* w1 = (const float*)d_in[4];
    const float* b1 = (const float*)d_in[5];
    const float* w2 = (const float*)d_in[6];
    const float* b2 = (const float*)d_in[7];
    const float* w3 = (const float*)d_in[8];
    const float* b3 = (const float*)d_in[9];
    const float* rootw = (const float*)d_in[10];
    const float* nnb = (const float*)d_in[11];
    const float* gatw = (const float*)d_in[12];
    const float* atts = (const float*)d_in[13];
    const float* attd = (const float*)d_in[14];
    const float* gatb = (const float*)d_in[15];
    const float* fc1w = (const float*)d_in[16];
    const float* fc1b = (const float*)d_in[17];
    float* out = (float*)d_out;

    cudaFuncSetAttribute(k2_edge, cudaFuncAttributeMaxDynamicSharedMemorySize, K2_SMEM);

    const int NB = (NN + 255) / 256;
    k1_prep<<<(25152 + 255) / 256, 256>>>(w1, b1, w2, w3, b2);
    k0_root<<<NB, 256>>>(x, rootw, nnb, b3);
    k2_edge<<<296, 256, K2_SMEM>>>(x, ei, ea);
    k3_node<<<NB, 256>>>(gatw, atts, attd);
    k4_edge<<<(NE + 255) / 256, 256>>>(ei);
    k5_node<<<NB, 256>>>();
    k6_edge<<<(NE * 4 + 255) / 256, 256>>>(ei);
    k7_node<<<NB, 256>>>(fc1w, fc1b, gatb, out);
}

// round 6
// speedup vs baseline: 4.0282x; 1.1875x over previous
#include <cuda_runtime.h>
#include <cuda_fp16.h>
#include <cstdint>

#define NN 50000
#define NE 800000
#define NT256 3125            // 256-edge tiles

// ---------------- device scratch ----------------------------------------------
__device__ float d_agg[NN * 16];
__device__ float d_b3t[NN * 16];
__device__ float d_xt[NN * 16];
__device__ float d_asrc[NN];
__device__ float d_adst[NN];
__device__ unsigned int d_menc[NN];
__device__ float d_z[NN];
__device__ float d_gout[NN * 16];
__device__ float d_ebuf[NE];
// packed weight images: B2P (8192 u32) | B3P (16384 u32) | w1P (512 f32) | b2 (64 f32)
__device__ unsigned d_wimg[25152];

// ---------------- helpers ------------------------------------------------------
__device__ __forceinline__ unsigned enc_f(float f) {
    unsigned u = __float_as_uint(f);
    return (u & 0x80000000u) ? ~u : (u | 0x80000000u);
}
__device__ __forceinline__ float dec_f(unsigned k) {
    return __uint_as_float((k & 0x80000000u) ? (k & 0x7fffffffu) : ~k);
}
__device__ __forceinline__ float lrelu(float v) { return v > 0.f ? v : 0.2f * v; }

__device__ __forceinline__ unsigned packh(float a, float b) {
    unsigned r;
    asm("cvt.rn.f16x2.f32 %0, %1, %2;" : "=r"(r) : "f"(b), "f"(a));
    return r;
}
__device__ __forceinline__ unsigned loh(unsigned hi, float a, float b) {
    float ha = __half2float(__ushort_as_half((unsigned short)(hi & 0xFFFFu)));
    float hb = __half2float(__ushort_as_half((unsigned short)(hi >> 16)));
    return packh(a - ha, b - hb);
}

__device__ __forceinline__ void mma16816(float* c, const unsigned* a,
                                         unsigned b0, unsigned b1) {
    asm volatile(
        "mma.sync.aligned.m16n8k16.row.col.f32.f16.f16.f32 "
        "{%0,%1,%2,%3}, {%4,%5,%6,%7}, {%8,%9}, {%0,%1,%2,%3};"
        : "+f"(c[0]), "+f"(c[1]), "+f"(c[2]), "+f"(c[3])
        : "r"(a[0]), "r"(a[1]), "r"(a[2]), "r"(a[3]), "r"(b0), "r"(b1));
}

// smem byte offsets inside k2
#define SM_B2P 0
#define SM_B3P 32768
#define SM_W1P 98304
#define SM_B2B 100352
#define K2_SMEM 100608

// ---------------- K1: pack weights into fragment-order hi/lo fp16 images -------
__global__ void k1_prep(const float* __restrict__ w1, const float* __restrict__ b1,
                        const float* __restrict__ w2, const float* __restrict__ w3,
                        const float* __restrict__ b2) {
    int t = blockIdx.x * blockDim.x + threadIdx.x;
    if (t >= 25152) return;
    if (t < 8192) {               // B2P from W2 [128,64]
        int j = t & 3, lane = (t >> 2) & 31, nt = (t >> 7) & 7, s = t >> 10;
        int kk = 16 * s + 2 * (lane & 3) + ((j & 1) ? 8 : 0);
        int n = 8 * nt + (lane >> 2);
        float va = w2[kk * 64 + n], vb = w2[(kk + 1) * 64 + n];
        unsigned hi = packh(va, vb);
        d_wimg[t] = (j < 2) ? hi : loh(hi, va, vb);
    } else if (t < 24576) {       // B3P from W3 [64,256]
        int u = t - 8192;
        int j = u & 3, lane = (u >> 2) & 31, nt = (u >> 7) & 31, s3 = u >> 12;
        int kk = 16 * s3 + 2 * (lane & 3) + ((j & 1) ? 8 : 0);
        int n = 8 * nt + (lane >> 2);
        float va = w3[kk * 256 + n], vb = w3[(kk + 1) * 256 + n];
        unsigned hi = packh(va, vb);
        d_wimg[t] = (j < 2) ? hi : loh(hi, va, vb);
    } else if (t < 25088) {       // w1P: [s][q][j][4] = {w1[0,c],w1[1,c],w1[2,c],b1[c]}
        int f = t - 24576;
        int comp = f & 3, j = (f >> 2) & 3, q = (f >> 4) & 3, s = f >> 6;
        int c = 16 * s + 2 * q + (j & 1) + (j >> 1) * 8;
        float v = (comp < 3) ? w1[comp * 128 + c] : b1[c];
        d_wimg[t] = __float_as_uint(v);
    } else {                      // b2
        d_wimg[t] = __float_as_uint(b2[t - 25088]);
    }
}

// ---------------- K0: agg init + b3 term (2 threads / node) --------------------
__global__ void k0_root(const float* __restrict__ x, const float* __restrict__ rw,
                        const float* __restrict__ nb, const float* __restrict__ b3) {
    int gid = blockIdx.x * blockDim.x + threadIdx.x;
    if (gid >= NN * 2) return;
    int n = gid >> 1, ob = (gid & 1) * 8;
    float xr[16];
#pragma unroll
    for (int i = 0; i < 16; i++) xr[i] = x[n * 16 + i];
#pragma unroll
    for (int oo = 0; oo < 8; oo++) {
        int o = ob + oo;
        float a = __ldg(&nb[o]);
        float b = 0.f;
#pragma unroll
        for (int i = 0; i < 16; i++) {
            a = fmaf(xr[i], __ldg(&rw[i * 16 + o]), a);
            b = fmaf(xr[i], __ldg(&b3[i * 16 + o]), b);
        }
        d_agg[n * 16 + o] = a;
        d_b3t[n * 16 + o] = b;
    }
}

// ---------------- K2: fused edge pipeline, 2 row-tiles per warp ----------------
__global__ void __launch_bounds__(256, 2)
k2_edge(const float* __restrict__ x, const int* __restrict__ ei,
        const float* __restrict__ ea) {
    extern __shared__ unsigned char smc[];
    int tid = threadIdx.x;
    {
        const uint4* src = (const uint4*)d_wimg;
        uint4* dst = (uint4*)smc;
        for (int i = tid; i < 6288; i += 256) dst[i] = src[i];
    }
    __syncthreads();

    const int w = tid >> 5, lane = tid & 31;
    const int q = lane & 3, l4 = lane >> 2;
    const int bq = 2 * q;
    const float* sw1 = (const float*)(smc + SM_W1P);
    const float* sb2 = (const float*)(smc + SM_B2B);

    for (int tile = blockIdx.x; tile < NT256; tile += gridDim.x) {
        const int base = (tile << 8) + (w << 5) + l4;   // rows base+{0,8,16,24}
        int srcv[4], dstv[4];
        float eav[4][3];
#pragma unroll
        for (int r = 0; r < 4; r++) {
            int e = base + 8 * r;
            srcv[r] = __ldg(&ei[e]);
            dstv[r] = __ldg(&ei[NE + e]);
            eav[r][0] = __ldg(&ea[(size_t)e * 3]);
            eav[r][1] = __ldg(&ea[(size_t)e * 3 + 1]);
            eav[r][2] = __ldg(&ea[(size_t)e * 3 + 2]);
        }

        // ---- L2 (fused L1): C2[m][16,64] for two m16 row-tiles ----
        float C2[2][8][4];
#pragma unroll
        for (int m = 0; m < 2; m++)
#pragma unroll
            for (int nt = 0; nt < 8; nt++)
#pragma unroll
                for (int v = 0; v < 4; v++) C2[m][nt][v] = 0.f;

#pragma unroll
        for (int s = 0; s < 8; s++) {
            float h[4][4];
#pragma unroll
            for (int j = 0; j < 4; j++) {
                float4 wf = *(const float4*)&sw1[(((s * 4 + q) * 4) + j) * 4];
#pragma unroll
                for (int r = 0; r < 4; r++)
                    h[r][j] = fmaxf(fmaf(eav[r][2], wf.z,
                               fmaf(eav[r][1], wf.y, fmaf(eav[r][0], wf.x, wf.w))), 0.f);
            }
            unsigned Ah[2][4];
#pragma unroll
            for (int m = 0; m < 2; m++) {
                Ah[m][0] = packh(h[2 * m][0], h[2 * m][1]);
                Ah[m][1] = packh(h[2 * m + 1][0], h[2 * m + 1][1]);
                Ah[m][2] = packh(h[2 * m][2], h[2 * m][3]);
                Ah[m][3] = packh(h[2 * m + 1][2], h[2 * m + 1][3]);
            }
#pragma unroll
            for (int nt = 0; nt < 8; nt++) {
                uint4 B = *(const uint4*)(smc + SM_B2P + (((s * 8 + nt) * 32 + lane) << 4));
#pragma unroll
                for (int m = 0; m < 2; m++) {
                    mma16816(C2[m][nt], Ah[m], B.x, B.y);
                    mma16816(C2[m][nt], Ah[m], B.z, B.w);
                }
            }
        }

        // ---- epilogue: +b2, relu -> A3 fragments ----
        unsigned A3h[2][4][4];
#pragma unroll
        for (int m = 0; m < 2; m++)
#pragma unroll
            for (int s3 = 0; s3 < 4; s3++) {
                int c = 16 * s3 + bq;
                float2 bA = *(const float2*)&sb2[c];
                float2 bB = *(const float2*)&sb2[c + 8];
                float v00 = fmaxf(C2[m][2 * s3][0] + bA.x, 0.f);
                float v01 = fmaxf(C2[m][2 * s3][1] + bA.y, 0.f);
                float v10 = fmaxf(C2[m][2 * s3][2] + bA.x, 0.f);
                float v11 = fmaxf(C2[m][2 * s3][3] + bA.y, 0.f);
                float v20 = fmaxf(C2[m][2 * s3 + 1][0] + bB.x, 0.f);
                float v21 = fmaxf(C2[m][2 * s3 + 1][1] + bB.y, 0.f);
                float v30 = fmaxf(C2[m][2 * s3 + 1][2] + bB.x, 0.f);
                float v31 = fmaxf(C2[m][2 * s3 + 1][3] + bB.y, 0.f);
                A3h[m][s3][0] = packh(v00, v01);
                A3h[m][s3][1] = packh(v10, v11);
                A3h[m][s3][2] = packh(v20, v21);
                A3h[m][s3][3] = packh(v30, v31);
            }

        // x[src] quarters (loaded after L2 to limit register pressure)
        float4 xq[4];
#pragma unroll
        for (int r = 0; r < 4; r++)
            xq[r] = *(const float4*)&x[(size_t)srcv[r] * 16 + 4 * q];

        // ---- L3 + einsum ----
        float macc[2][2][4];
#pragma unroll
        for (int m = 0; m < 2; m++)
#pragma unroll
            for (int r2 = 0; r2 < 2; r2++)
#pragma unroll
                for (int jj = 0; jj < 4; jj++) macc[m][r2][jj] = 0.f;

#pragma unroll
        for (int grp = 0; grp < 8; grp++) {
            float C3[2][4][4];
#pragma unroll
            for (int m = 0; m < 2; m++)
#pragma unroll
                for (int t = 0; t < 4; t++)
#pragma unroll
                    for (int v = 0; v < 4; v++) C3[m][t][v] = 0.f;
#pragma unroll
            for (int s3 = 0; s3 < 4; s3++) {
#pragma unroll
                for (int t = 0; t < 4; t++) {
                    int nt = grp * 4 + t;
                    uint4 B = *(const uint4*)(smc + SM_B3P + (((s3 * 32 + nt) * 32 + lane) << 4));
#pragma unroll
                    for (int m = 0; m < 2; m++) {
                        mma16816(C3[m][t], A3h[m][s3], B.x, B.y);
                        mma16816(C3[m][t], A3h[m][s3], B.z, B.w);
                    }
                }
            }
#pragma unroll
            for (int t = 0; t < 4; t++) {
                const int nt = grp * 4 + t;
                const int i = nt >> 1;
                const int sl = (lane & ~3) | (i >> 2);
                float xv[4];
#pragma unroll
                for (int r = 0; r < 4; r++) {
                    float own;
                    switch (i & 3) {
                        case 0: own = xq[r].x; break;
                        case 1: own = xq[r].y; break;
                        case 2: own = xq[r].z; break;
                        default: own = xq[r].w; break;
                    }
                    xv[r] = __shfl_sync(0xffffffffu, own, sl);
                }
                const int p = nt & 1;
#pragma unroll
                for (int m = 0; m < 2; m++) {
                    macc[m][0][2 * p]     = fmaf(C3[m][t][0], xv[2 * m], macc[m][0][2 * p]);
                    macc[m][0][2 * p + 1] = fmaf(C3[m][t][1], xv[2 * m], macc[m][0][2 * p + 1]);
                    macc[m][1][2 * p]     = fmaf(C3[m][t][2], xv[2 * m + 1], macc[m][1][2 * p]);
                    macc[m][1][2 * p + 1] = fmaf(C3[m][t][3], xv[2 * m + 1], macc[m][1][2 * p + 1]);
                }
            }
        }

        // ---- flush: + b3t[src], atomic into d_agg[dst] ----
#pragma unroll
        for (int m = 0; m < 2; m++)
#pragma unroll
            for (int r2 = 0; r2 < 2; r2++) {
                int r = 2 * m + r2;
                float2 pA = *(const float2*)&d_b3t[(size_t)srcv[r] * 16 + bq];
                float2 pB = *(const float2*)&d_b3t[(size_t)srcv[r] * 16 + bq + 8];
                float* a = &d_agg[(size_t)dstv[r] * 16];
                atomicAdd(a + bq,     macc[m][r2][0] + pA.x);
                atomicAdd(a + bq + 1, macc[m][r2][1] + pA.y);
                atomicAdd(a + bq + 8, macc[m][r2][2] + pB.x);
                atomicAdd(a + bq + 9, macc[m][r2][3] + pB.y);
            }
    }
}

// ---------------- K3: x1 = relu(agg); xt = x1@gat_w (2 threads / node) ---------
__global__ void k3_node(const float* __restrict__ gw, const float* __restrict__ as_,
                        const float* __restrict__ ad_) {
    __shared__ float sw[256], sa[16], sbv[16];
    int tid = threadIdx.x;
    if (tid < 256) sw[tid] = gw[tid];
    if (tid < 16) { sa[tid] = as_[tid]; sbv[tid] = ad_[tid]; }
    __syncthreads();
    int gid = blockIdx.x * blockDim.x + tid;
    if (gid >= NN * 2) return;
    int n = gid >> 1, ob = (gid & 1) * 8;
    float x1[16];
#pragma unroll
    for (int i = 0; i < 16; i++) x1[i] = fmaxf(d_agg[n * 16 + i], 0.f);
    float asrc = 0.f, adst = 0.f;
#pragma unroll
    for (int oo = 0; oo < 8; oo++) {
        int o = ob + oo;
        float v = 0.f;
#pragma unroll
        for (int i = 0; i < 16; i++) v = fmaf(x1[i], sw[i * 16 + o], v);
        d_xt[n * 16 + o] = v;
        asrc = fmaf(v, sa[o], asrc);
        adst = fmaf(v, sbv[o], adst);
    }
    asrc += __shfl_xor_sync(0xffffffffu, asrc, 1);
    adst += __shfl_xor_sync(0xffffffffu, adst, 1);
    if ((gid & 1) == 0) {
        d_asrc[n] = asrc;
        d_adst[n] = adst;
        d_menc[n] = enc_f(lrelu(asrc + adst));   // self-loop seeds the max
    }
}

// ---------------- K4: edge logits + segment max --------------------------------
__global__ void k4_edge(const int* __restrict__ ei) {
    int e = blockIdx.x * blockDim.x + threadIdx.x;
    if (e >= NE) return;
    int s = ei[e], d = ei[NE + e];
    float v = lrelu(d_asrc[s] + d_adst[d]);
    d_ebuf[e] = v;
    atomicMax(&d_menc[d], enc_f(v));
}

// ---------------- K5: init z / gout with self-loop (4 threads / node) ----------
__global__ void k5_node() {
    int gid = blockIdx.x * blockDim.x + threadIdx.x;
    if (gid >= NN * 4) return;
    int n = gid >> 2, part = gid & 3;
    float m = dec_f(d_menc[n]);
    float es = lrelu(d_asrc[n] + d_adst[n]);
    float wv = __expf(es - m);
    if (part == 0) d_z[n] = wv;
    float4 xv = *(const float4*)&d_xt[(size_t)n * 16 + part * 4];
    float4 r;
    r.x = wv * xv.x; r.y = wv * xv.y; r.z = wv * xv.z; r.w = wv * xv.w;
    *(float4*)&d_gout[(size_t)n * 16 + part * 4] = r;
}

// ---------------- K6: softmax-weighted scatter (4 threads / edge) --------------
__global__ void k6_edge(const int* __restrict__ ei) {
    int gid = blockIdx.x * blockDim.x + threadIdx.x;
    if (gid >= NE * 4) return;
    int e = gid >> 2, part = gid & 3;
    int s = ei[e], d = ei[NE + e];
    float wv = __expf(d_ebuf[e] - dec_f(d_menc[d]));
    float4 xv = *(const float4*)&d_xt[(size_t)s * 16 + part * 4];
    float* gp = &d_gout[(size_t)d * 16 + part * 4];
    atomicAdd(gp,     wv * xv.x);
    atomicAdd(gp + 1, wv * xv.y);
    atomicAdd(gp + 2, wv * xv.z);
    atomicAdd(gp + 3, wv * xv.w);
    if (part == 0) atomicAdd(&d_z[d], wv);
}

// ---------------- K7: normalize, gat bias, relu, fc1, relu (4 thr / node) ------
__global__ void k7_node(const float* __restrict__ fw, const float* __restrict__ fb,
                        const float* __restrict__ gb, float* __restrict__ out) {
    __shared__ float sw[1024], sbv[64], sgb[16];
    int tid = threadIdx.x;
    for (int i = tid; i < 1024; i += blockDim.x) sw[i] = fw[i];
    if (tid < 64) sbv[tid] = fb[tid];
    if (tid < 16) sgb[tid] = gb[tid];
    __syncthreads();
    int gid = blockIdx.x * blockDim.x + tid;
    if (gid >= NN * 4) return;
    int n = gid >> 2, jb = (gid & 3) * 16;
    float inv = 1.f / d_z[n];
    float x2[16];
#pragma unroll
    for (int i = 0; i < 16; i++)
        x2[i] = fmaxf(d_gout[n * 16 + i] * inv + sgb[i], 0.f);
#pragma unroll 4
    for (int jj = 0; jj < 16; jj++) {
        int j = jb + jj;
        float a = sbv[j];
#pragma unroll
        for (int i = 0; i < 16; i++) a = fmaf(x2[i], sw[i * 64 + j], a);
        out[(size_t)n * 64 + j] = fmaxf(a, 0.f);
    }
}

// ---------------- launch -------------------------------------------------------
extern "C" void kernel_launch(void* const* d_in, const int* in_sizes, int n_in,
                              void* d_out, int out_size) {
    const float* x = (const float*)d_in[0];
    const int* ei = (const int*)d_in[1];
    const float* ea = (const float*)d_in[2];
    const float* w1 = (const float*)d_in[4];
    const float* b1 = (const float*)d_in[5];
    const float* w2 = (const float*)d_in[6];
    const float* b2 = (const float*)d_in[7];
    const float* w3 = (const float*)d_in[8];
    const float* b3 = (const float*)d_in[9];
    const float* rootw = (const float*)d_in[10];
    const float* nnb = (const float*)d_in[11];
    const float* gatw = (const float*)d_in[12];
    const float* atts = (const float*)d_in[13];
    const float* attd = (const float*)d_in[14];
    const float* gatb = (const float*)d_in[15];
    const float* fc1w = (const float*)d_in[16];
    const float* fc1b = (const float*)d_in[17];
    float* out = (float*)d_out;

    cudaFuncSetAttribute(k2_edge, cudaFuncAttributeMaxDynamicSharedMemorySize, K2_SMEM);

    k1_prep<<<(25152 + 255) / 256, 256>>>(w1, b1, w2, w3, b2);
    k0_root<<<(NN * 2 + 255) / 256, 256>>>(x, rootw, nnb, b3);
    k2_edge<<<296, 256, K2_SMEM>>>(x, ei, ea);
    k3_node<<<(NN * 2 + 255) / 256, 256>>>(gatw, atts, attd);
    k4_edge<<<(NE + 255) / 256, 256>>>(ei);
    k5_node<<<(NN * 4 + 255) / 256, 256>>>();
    k6_edge<<<(NE * 4 + 255) / 256, 256>>>(ei);
    k7_node<<<(NN * 4 + 255) / 256, 256>>>(fc1w, fc1b, gatb, out);
}

// round 7
// speedup vs baseline: 4.3614x; 1.0827x over previous
#include <cuda_runtime.h>
#include <cuda_fp16.h>
#include <cstdint>

#define NN 50000
#define NE 800000
#define NT256 3125            // 256-edge tiles

// ---------------- device scratch ----------------------------------------------
__device__ float d_agg[NN * 16];
__device__ float d_b3t[NN * 16];
__device__ float d_xt[NN * 16];
__device__ float d_asrc[NN];
__device__ float d_adst[NN];
__device__ unsigned int d_menc[NN];
__device__ float d_z[NN];
__device__ float d_gout[NN * 16];
__device__ float d_ebuf[NE];
// packed weight images: B2P (8192 u32) | B3P (16384 u32) | w1P (512 f32) | b2 (64 f32)
__device__ unsigned d_wimg[25152];

// ---------------- helpers ------------------------------------------------------
__device__ __forceinline__ unsigned enc_f(float f) {
    unsigned u = __float_as_uint(f);
    return (u & 0x80000000u) ? ~u : (u | 0x80000000u);
}
__device__ __forceinline__ float dec_f(unsigned k) {
    return __uint_as_float((k & 0x80000000u) ? (k & 0x7fffffffu) : ~k);
}
__device__ __forceinline__ float lrelu(float v) { return v > 0.f ? v : 0.2f * v; }

__device__ __forceinline__ unsigned packh(float a, float b) {
    unsigned r;
    asm("cvt.rn.f16x2.f32 %0, %1, %2;" : "=r"(r) : "f"(b), "f"(a));
    return r;
}
__device__ __forceinline__ unsigned loh(unsigned hi, float a, float b) {
    float ha = __half2float(__ushort_as_half((unsigned short)(hi & 0xFFFFu)));
    float hb = __half2float(__ushort_as_half((unsigned short)(hi >> 16)));
    return packh(a - ha, b - hb);
}

__device__ __forceinline__ void mma16816(float* c, const unsigned* a,
                                         unsigned b0, unsigned b1) {
    asm volatile(
        "mma.sync.aligned.m16n8k16.row.col.f32.f16.f16.f32 "
        "{%0,%1,%2,%3}, {%4,%5,%6,%7}, {%8,%9}, {%0,%1,%2,%3};"
        : "+f"(c[0]), "+f"(c[1]), "+f"(c[2]), "+f"(c[3])
        : "r"(a[0]), "r"(a[1]), "r"(a[2]), "r"(a[3]), "r"(b0), "r"(b1));
}

// vector global reductions (sm_90+ baseline)
__device__ __forceinline__ void redv2(float* p, float a, float b) {
    asm volatile("red.global.add.v2.f32 [%0], {%1, %2};"
                 :: "l"(p), "f"(a), "f"(b) : "memory");
}
__device__ __forceinline__ void redv4(float* p, float a, float b, float c, float d) {
    asm volatile("red.global.add.v4.f32 [%0], {%1, %2, %3, %4};"
                 :: "l"(p), "f"(a), "f"(b), "f"(c), "f"(d) : "memory");
}

// smem byte offsets inside k2
#define SM_B2P 0
#define SM_B3P 32768
#define SM_W1P 98304
#define SM_B2B 100352
#define K2_SMEM 100608

// ---------------- K1: pack weights into fragment-order hi/lo fp16 images -------
__global__ void k1_prep(const float* __restrict__ w1, const float* __restrict__ b1,
                        const float* __restrict__ w2, const float* __restrict__ w3,
                        const float* __restrict__ b2) {
    int t = blockIdx.x * blockDim.x + threadIdx.x;
    if (t >= 25152) return;
    if (t < 8192) {               // B2P from W2 [128,64]
        int j = t & 3, lane = (t >> 2) & 31, nt = (t >> 7) & 7, s = t >> 10;
        int kk = 16 * s + 2 * (lane & 3) + ((j & 1) ? 8 : 0);
        int n = 8 * nt + (lane >> 2);
        float va = w2[kk * 64 + n], vb = w2[(kk + 1) * 64 + n];
        unsigned hi = packh(va, vb);
        d_wimg[t] = (j < 2) ? hi : loh(hi, va, vb);
    } else if (t < 24576) {       // B3P from W3 [64,256]
        int u = t - 8192;
        int j = u & 3, lane = (u >> 2) & 31, nt = (u >> 7) & 31, s3 = u >> 12;
        int kk = 16 * s3 + 2 * (lane & 3) + ((j & 1) ? 8 : 0);
        int n = 8 * nt + (lane >> 2);
        float va = w3[kk * 256 + n], vb = w3[(kk + 1) * 256 + n];
        unsigned hi = packh(va, vb);
        d_wimg[t] = (j < 2) ? hi : loh(hi, va, vb);
    } else if (t < 25088) {       // w1P: [s][q][j][4] = {w1[0,c],w1[1,c],w1[2,c],b1[c]}
        int f = t - 24576;
        int comp = f & 3, j = (f >> 2) & 3, q = (f >> 4) & 3, s = f >> 6;
        int c = 16 * s + 2 * q + (j & 1) + (j >> 1) * 8;
        float v = (comp < 3) ? w1[comp * 128 + c] : b1[c];
        d_wimg[t] = __float_as_uint(v);
    } else {                      // b2
        d_wimg[t] = __float_as_uint(b2[t - 25088]);
    }
}

// ---------------- K0: agg init + b3 term + zero gout/z (4 threads / node) ------
__global__ void k0_root(const float* __restrict__ x, const float* __restrict__ rw,
                        const float* __restrict__ nb, const float* __restrict__ b3) {
    int gid = blockIdx.x * blockDim.x + threadIdx.x;
    if (gid >= NN * 4) return;
    int n = gid >> 2, ob = (gid & 3) * 4;
    float xr[16];
#pragma unroll
    for (int i = 0; i < 16; i += 4) {
        float4 v = __ldg((const float4*)&x[(size_t)n * 16 + i]);
        xr[i] = v.x; xr[i + 1] = v.y; xr[i + 2] = v.z; xr[i + 3] = v.w;
    }
    float av[4], bv[4];
#pragma unroll
    for (int oo = 0; oo < 4; oo++) {
        int o = ob + oo;
        float a = __ldg(&nb[o]);
        float b = 0.f;
#pragma unroll
        for (int i = 0; i < 16; i++) {
            a = fmaf(xr[i], __ldg(&rw[i * 16 + o]), a);
            b = fmaf(xr[i], __ldg(&b3[i * 16 + o]), b);
        }
        av[oo] = a; bv[oo] = b;
    }
    *(float4*)&d_agg[(size_t)n * 16 + ob] = make_float4(av[0], av[1], av[2], av[3]);
    *(float4*)&d_b3t[(size_t)n * 16 + ob] = make_float4(bv[0], bv[1], bv[2], bv[3]);
    *(float4*)&d_gout[(size_t)n * 16 + ob] = make_float4(0.f, 0.f, 0.f, 0.f);
    if ((gid & 3) == 0) d_z[n] = 0.f;
}

// ---------------- K2: fused edge pipeline, 2 row-tiles per warp ----------------
__global__ void __launch_bounds__(256, 2)
k2_edge(const float* __restrict__ x, const int* __restrict__ ei,
        const float* __restrict__ ea) {
    extern __shared__ unsigned char smc[];
    int tid = threadIdx.x;
    {
        const uint4* src = (const uint4*)d_wimg;
        uint4* dst = (uint4*)smc;
        for (int i = tid; i < 6288; i += 256) dst[i] = src[i];
    }
    __syncthreads();

    const int w = tid >> 5, lane = tid & 31;
    const int q = lane & 3, l4 = lane >> 2;
    const int bq = 2 * q;
    const float* sw1 = (const float*)(smc + SM_W1P);
    const float* sb2 = (const float*)(smc + SM_B2B);

    for (int tile = blockIdx.x; tile < NT256; tile += gridDim.x) {
        const int base = (tile << 8) + (w << 5) + l4;   // rows base+{0,8,16,24}
        int srcv[4], dstv[4];
        float eav[4][3];
#pragma unroll
        for (int r = 0; r < 4; r++) {
            int e = base + 8 * r;
            srcv[r] = __ldg(&ei[e]);
            dstv[r] = __ldg(&ei[NE + e]);
            eav[r][0] = __ldg(&ea[(size_t)e * 3]);
            eav[r][1] = __ldg(&ea[(size_t)e * 3 + 1]);
            eav[r][2] = __ldg(&ea[(size_t)e * 3 + 2]);
        }

        // ---- L2 (fused L1): C2[m][16,64] for two m16 row-tiles ----
        float C2[2][8][4];
#pragma unroll
        for (int m = 0; m < 2; m++)
#pragma unroll
            for (int nt = 0; nt < 8; nt++)
#pragma unroll
                for (int v = 0; v < 4; v++) C2[m][nt][v] = 0.f;

#pragma unroll
        for (int s = 0; s < 8; s++) {
            float h[4][4];
#pragma unroll
            for (int j = 0; j < 4; j++) {
                float4 wf = *(const float4*)&sw1[(((s * 4 + q) * 4) + j) * 4];
#pragma unroll
                for (int r = 0; r < 4; r++)
                    h[r][j] = fmaxf(fmaf(eav[r][2], wf.z,
                               fmaf(eav[r][1], wf.y, fmaf(eav[r][0], wf.x, wf.w))), 0.f);
            }
            unsigned Ah[2][4];
#pragma unroll
            for (int m = 0; m < 2; m++) {
                Ah[m][0] = packh(h[2 * m][0], h[2 * m][1]);
                Ah[m][1] = packh(h[2 * m + 1][0], h[2 * m + 1][1]);
                Ah[m][2] = packh(h[2 * m][2], h[2 * m][3]);
                Ah[m][3] = packh(h[2 * m + 1][2], h[2 * m + 1][3]);
            }
#pragma unroll
            for (int nt = 0; nt < 8; nt++) {
                uint4 B = *(const uint4*)(smc + SM_B2P + (((s * 8 + nt) * 32 + lane) << 4));
#pragma unroll
                for (int m = 0; m < 2; m++) {
                    mma16816(C2[m][nt], Ah[m], B.x, B.y);
                    mma16816(C2[m][nt], Ah[m], B.z, B.w);
                }
            }
        }

        // ---- epilogue: +b2, relu -> A3 fragments ----
        unsigned A3h[2][4][4];
#pragma unroll
        for (int m = 0; m < 2; m++)
#pragma unroll
            for (int s3 = 0; s3 < 4; s3++) {
                int c = 16 * s3 + bq;
                float2 bA = *(const float2*)&sb2[c];
                float2 bB = *(const float2*)&sb2[c + 8];
                float v00 = fmaxf(C2[m][2 * s3][0] + bA.x, 0.f);
                float v01 = fmaxf(C2[m][2 * s3][1] + bA.y, 0.f);
                float v10 = fmaxf(C2[m][2 * s3][2] + bA.x, 0.f);
                float v11 = fmaxf(C2[m][2 * s3][3] + bA.y, 0.f);
                float v20 = fmaxf(C2[m][2 * s3 + 1][0] + bB.x, 0.f);
                float v21 = fmaxf(C2[m][2 * s3 + 1][1] + bB.y, 0.f);
                float v30 = fmaxf(C2[m][2 * s3 + 1][2] + bB.x, 0.f);
                float v31 = fmaxf(C2[m][2 * s3 + 1][3] + bB.y, 0.f);
                A3h[m][s3][0] = packh(v00, v01);
                A3h[m][s3][1] = packh(v10, v11);
                A3h[m][s3][2] = packh(v20, v21);
                A3h[m][s3][3] = packh(v30, v31);
            }

        // x[src] quarters (loaded after L2 to limit register pressure)
        float4 xq[4];
#pragma unroll
        for (int r = 0; r < 4; r++)
            xq[r] = *(const float4*)&x[(size_t)srcv[r] * 16 + 4 * q];

        // ---- L3 + einsum ----
        float macc[2][2][4];
#pragma unroll
        for (int m = 0; m < 2; m++)
#pragma unroll
            for (int r2 = 0; r2 < 2; r2++)
#pragma unroll
                for (int jj = 0; jj < 4; jj++) macc[m][r2][jj] = 0.f;

#pragma unroll
        for (int grp = 0; grp < 8; grp++) {
            float C3[2][4][4];
#pragma unroll
            for (int m = 0; m < 2; m++)
#pragma unroll
                for (int t = 0; t < 4; t++)
#pragma unroll
                    for (int v = 0; v < 4; v++) C3[m][t][v] = 0.f;
#pragma unroll
            for (int s3 = 0; s3 < 4; s3++) {
#pragma unroll
                for (int t = 0; t < 4; t++) {
                    int nt = grp * 4 + t;
                    uint4 B = *(const uint4*)(smc + SM_B3P + (((s3 * 32 + nt) * 32 + lane) << 4));
#pragma unroll
                    for (int m = 0; m < 2; m++) {
                        mma16816(C3[m][t], A3h[m][s3], B.x, B.y);
                        mma16816(C3[m][t], A3h[m][s3], B.z, B.w);
                    }
                }
            }
#pragma unroll
            for (int t = 0; t < 4; t++) {
                const int nt = grp * 4 + t;
                const int i = nt >> 1;
                const int sl = (lane & ~3) | (i >> 2);
                float xv[4];
#pragma unroll
                for (int r = 0; r < 4; r++) {
                    float own;
                    switch (i & 3) {
                        case 0: own = xq[r].x; break;
                        case 1: own = xq[r].y; break;
                        case 2: own = xq[r].z; break;
                        default: own = xq[r].w; break;
                    }
                    xv[r] = __shfl_sync(0xffffffffu, own, sl);
                }
                const int p = nt & 1;
#pragma unroll
                for (int m = 0; m < 2; m++) {
                    macc[m][0][2 * p]     = fmaf(C3[m][t][0], xv[2 * m], macc[m][0][2 * p]);
                    macc[m][0][2 * p + 1] = fmaf(C3[m][t][1], xv[2 * m], macc[m][0][2 * p + 1]);
                    macc[m][1][2 * p]     = fmaf(C3[m][t][2], xv[2 * m + 1], macc[m][1][2 * p]);
                    macc[m][1][2 * p + 1] = fmaf(C3[m][t][3], xv[2 * m + 1], macc[m][1][2 * p + 1]);
                }
            }
        }

        // ---- flush: + b3t[src], vector-red into d_agg[dst] ----
#pragma unroll
        for (int m = 0; m < 2; m++)
#pragma unroll
            for (int r2 = 0; r2 < 2; r2++) {
                int r = 2 * m + r2;
                float2 pA = *(const float2*)&d_b3t[(size_t)srcv[r] * 16 + bq];
                float2 pB = *(const float2*)&d_b3t[(size_t)srcv[r] * 16 + bq + 8];
                float* a = &d_agg[(size_t)dstv[r] * 16];
                redv2(a + bq,     macc[m][r2][0] + pA.x, macc[m][r2][1] + pA.y);
                redv2(a + bq + 8, macc[m][r2][2] + pB.x, macc[m][r2][3] + pB.y);
            }
    }
}

// ---------------- K3: x1 = relu(agg); xt = x1@gat_w (4 threads / node) ---------
__global__ void k3_node(const float* __restrict__ gw, const float* __restrict__ as_,
                        const float* __restrict__ ad_) {
    __shared__ float sw[256], sa[16], sbv[16];
    int tid = threadIdx.x;
    if (tid < 256) sw[tid] = gw[tid];
    if (tid < 16) { sa[tid] = as_[tid]; sbv[tid] = ad_[tid]; }
    __syncthreads();
    int gid = blockIdx.x * blockDim.x + tid;
    if (gid >= NN * 4) return;
    int n = gid >> 2, ob = (gid & 3) * 4;
    float x1[16];
#pragma unroll
    for (int i = 0; i < 16; i++) x1[i] = fmaxf(d_agg[n * 16 + i], 0.f);
    float asrc = 0.f, adst = 0.f;
    float vo[4];
#pragma unroll
    for (int oo = 0; oo < 4; oo++) {
        int o = ob + oo;
        float v = 0.f;
#pragma unroll
        for (int i = 0; i < 16; i++) v = fmaf(x1[i], sw[i * 16 + o], v);
        vo[oo] = v;
        asrc = fmaf(v, sa[o], asrc);
        adst = fmaf(v, sbv[o], adst);
    }
    *(float4*)&d_xt[(size_t)n * 16 + ob] = make_float4(vo[0], vo[1], vo[2], vo[3]);
    asrc += __shfl_xor_sync(0xffffffffu, asrc, 1);
    adst += __shfl_xor_sync(0xffffffffu, adst, 1);
    asrc += __shfl_xor_sync(0xffffffffu, asrc, 2);
    adst += __shfl_xor_sync(0xffffffffu, adst, 2);
    if ((gid & 3) == 0) {
        d_asrc[n] = asrc;
        d_adst[n] = adst;
        d_menc[n] = enc_f(lrelu(asrc + adst));   // self-loop seeds the max
    }
}

// ---------------- K4: edge logits + segment max --------------------------------
__global__ void k4_edge(const int* __restrict__ ei) {
    int e = blockIdx.x * blockDim.x + threadIdx.x;
    if (e >= NE) return;
    int s = ei[e], d = ei[NE + e];
    float v = lrelu(d_asrc[s] + d_adst[d]);
    d_ebuf[e] = v;
    atomicMax(&d_menc[d], enc_f(v));
}

// ---------------- K6: softmax-weighted scatter (4 threads / edge, red.v4) ------
__global__ void k6_edge(const int* __restrict__ ei) {
    int gid = blockIdx.x * blockDim.x + threadIdx.x;
    if (gid >= NE * 4) return;
    int e = gid >> 2, part = gid & 3;
    int s = ei[e], d = ei[NE + e];
    float wv = __expf(d_ebuf[e] - dec_f(d_menc[d]));
    float4 xv = *(const float4*)&d_xt[(size_t)s * 16 + part * 4];
    redv4(&d_gout[(size_t)d * 16 + part * 4],
          wv * xv.x, wv * xv.y, wv * xv.z, wv * xv.w);
    if (part == 0) atomicAdd(&d_z[d], wv);
}

// ---------------- K7: self-loop fold + normalize + fc1 (4 thr / node) ----------
__global__ void k7_node(const float* __restrict__ fw, const float* __restrict__ fb,
                        const float* __restrict__ gb, float* __restrict__ out) {
    __shared__ float sw[1024], sbv[64], sgb[16];
    int tid = threadIdx.x;
    for (int i = tid; i < 1024; i += blockDim.x) sw[i] = fw[i];
    if (tid < 64) sbv[tid] = fb[tid];
    if (tid < 16) sgb[tid] = gb[tid];
    __syncthreads();
    int gid = blockIdx.x * blockDim.x + tid;
    if (gid >= NN * 4) return;
    int n = gid >> 2, jb = (gid & 3) * 16;
    float m = dec_f(d_menc[n]);
    float wself = __expf(lrelu(d_asrc[n] + d_adst[n]) - m);
    float inv = 1.f / (d_z[n] + wself);
    float x2[16];
#pragma unroll
    for (int i = 0; i < 16; i++) {
        float g = d_gout[n * 16 + i] + wself * d_xt[n * 16 + i];
        x2[i] = fmaxf(g * inv + sgb[i], 0.f);
    }
#pragma unroll 4
    for (int jj = 0; jj < 16; jj++) {
        int j = jb + jj;
        float a = sbv[j];
#pragma unroll
        for (int i = 0; i < 16; i++) a = fmaf(x2[i], sw[i * 64 + j], a);
        out[(size_t)n * 64 + j] = fmaxf(a, 0.f);
    }
}

// ---------------- launch -------------------------------------------------------
extern "C" void kernel_launch(void* const* d_in, const int* in_sizes, int n_in,
                              void* d_out, int out_size) {
    const float* x = (const float*)d_in[0];
    const int* ei = (const int*)d_in[1];
    const float* ea = (const float*)d_in[2];
    const float* w1 = (const float*)d_in[4];
    const float* b1 = (const float*)d_in[5];
    const float* w2 = (const float*)d_in[6];
    const float* b2 = (const float*)d_in[7];
    const float* w3 = (const float*)d_in[8];
    const float* b3 = (const float*)d_in[9];
    const float* rootw = (const float*)d_in[10];
    const float* nnb = (const float*)d_in[11];
    const float* gatw = (const float*)d_in[12];
    const float* atts = (const float*)d_in[13];
    const float* attd = (const float*)d_in[14];
    const float* gatb = (const float*)d_in[15];
    const float* fc1w = (const float*)d_in[16];
    const float* fc1b = (const float*)d_in[17];
    float* out = (float*)d_out;

    cudaFuncSetAttribute(k2_edge, cudaFuncAttributeMaxDynamicSharedMemorySize, K2_SMEM);

    k1_prep<<<(25152 + 255) / 256, 256>>>(w1, b1, w2, w3, b2);
    k0_root<<<(NN * 4 + 255) / 256, 256>>>(x, rootw, nnb, b3);
    k2_edge<<<296, 256, K2_SMEM>>>(x, ei, ea);
    k3_node<<<(NN * 4 + 255) / 256, 256>>>(gatw, atts, attd);
    k4_edge<<<(NE + 255) / 256, 256>>>(ei);
    k6_edge<<<(NE * 4 + 255) / 256, 256>>>(ei);
    k7_node<<<(NN * 4 + 255) / 256, 256>>>(fc1w, fc1b, gatb, out);
}

// round 8
// speedup vs baseline: 5.3110x; 1.2177x over previous
#include <cuda_runtime.h>
#include <cuda_fp16.h>
#include <cstdint>

#define NN 50000
#define NE 800000
#define NT256 3125            // 256-edge tiles

// ---------------- device scratch ----------------------------------------------
__device__ float d_agg[NN * 16];
__device__ float d_b3t[NN * 16];
__device__ float d_xt[NN * 16];
__device__ float d_asrc[NN];
__device__ float d_adst[NN];
__device__ unsigned int d_menc[NN];
__device__ float d_z[NN];
__device__ float d_gout[NN * 16];
__device__ float d_ebuf[NE];
// packed weight images: B2P (8192 u32) | B3P (16384 u32) | w1P (512 f32) | b2 (64 f32)
__device__ unsigned d_wimg[25152];

// ---------------- helpers ------------------------------------------------------
__device__ __forceinline__ unsigned enc_f(float f) {
    unsigned u = __float_as_uint(f);
    return (u & 0x80000000u) ? ~u : (u | 0x80000000u);
}
__device__ __forceinline__ float dec_f(unsigned k) {
    return __uint_as_float((k & 0x80000000u) ? (k & 0x7fffffffu) : ~k);
}
__device__ __forceinline__ float lrelu(float v) { return v > 0.f ? v : 0.2f * v; }

__device__ __forceinline__ unsigned packh(float a, float b) {
    unsigned r;
    asm("cvt.rn.f16x2.f32 %0, %1, %2;" : "=r"(r) : "f"(b), "f"(a));
    return r;
}
__device__ __forceinline__ unsigned loh(unsigned hi, float a, float b) {
    float ha = __half2float(__ushort_as_half((unsigned short)(hi & 0xFFFFu)));
    float hb = __half2float(__ushort_as_half((unsigned short)(hi >> 16)));
    return packh(a - ha, b - hb);
}

__device__ __forceinline__ void mma16816(float* c, const unsigned* a,
                                         unsigned b0, unsigned b1) {
    asm volatile(
        "mma.sync.aligned.m16n8k16.row.col.f32.f16.f16.f32 "
        "{%0,%1,%2,%3}, {%4,%5,%6,%7}, {%8,%9}, {%0,%1,%2,%3};"
        : "+f"(c[0]), "+f"(c[1]), "+f"(c[2]), "+f"(c[3])
        : "r"(a[0]), "r"(a[1]), "r"(a[2]), "r"(a[3]), "r"(b0), "r"(b1));
}

// vector global reductions (sm_90+ baseline)
__device__ __forceinline__ void redv2(float* p, float a, float b) {
    asm volatile("red.global.add.v2.f32 [%0], {%1, %2};"
                 :: "l"(p), "f"(a), "f"(b) : "memory");
}
__device__ __forceinline__ void redv4(float* p, float a, float b, float c, float d) {
    asm volatile("red.global.add.v4.f32 [%0], {%1, %2, %3, %4};"
                 :: "l"(p), "f"(a), "f"(b), "f"(c), "f"(d) : "memory");
}

// smem byte offsets inside k2
#define SM_B2P 0
#define SM_B3P 32768
#define SM_W1P 98304
#define SM_B2B 100352
#define K2_SMEM 100608

// ---------------- K1: pack weights into fragment-order hi/lo fp16 images -------
__global__ void k1_prep(const float* __restrict__ w1, const float* __restrict__ b1,
                        const float* __restrict__ w2, const float* __restrict__ w3,
                        const float* __restrict__ b2) {
    int t = blockIdx.x * blockDim.x + threadIdx.x;
    if (t >= 25152) return;
    if (t < 8192) {               // B2P from W2 [128,64]
        int j = t & 3, lane = (t >> 2) & 31, nt = (t >> 7) & 7, s = t >> 10;
        int kk = 16 * s + 2 * (lane & 3) + ((j & 1) ? 8 : 0);
        int n = 8 * nt + (lane >> 2);
        float va = w2[kk * 64 + n], vb = w2[(kk + 1) * 64 + n];
        unsigned hi = packh(va, vb);
        d_wimg[t] = (j < 2) ? hi : loh(hi, va, vb);
    } else if (t < 24576) {       // B3P from W3 [64,256]
        int u = t - 8192;
        int j = u & 3, lane = (u >> 2) & 31, nt = (u >> 7) & 31, s3 = u >> 12;
        int kk = 16 * s3 + 2 * (lane & 3) + ((j & 1) ? 8 : 0);
        int n = 8 * nt + (lane >> 2);
        float va = w3[kk * 256 + n], vb = w3[(kk + 1) * 256 + n];
        unsigned hi = packh(va, vb);
        d_wimg[t] = (j < 2) ? hi : loh(hi, va, vb);
    } else if (t < 25088) {       // w1P: [s][q][j][4] = {w1[0,c],w1[1,c],w1[2,c],b1[c]}
        int f = t - 24576;
        int comp = f & 3, j = (f >> 2) & 3, q = (f >> 4) & 3, s = f >> 6;
        int c = 16 * s + 2 * q + (j & 1) + (j >> 1) * 8;
        float v = (comp < 3) ? w1[comp * 128 + c] : b1[c];
        d_wimg[t] = __float_as_uint(v);
    } else {                      // b2
        d_wimg[t] = __float_as_uint(b2[t - 25088]);
    }
}

// ---------------- K0: agg init + b3 term + zero gout/z (4 threads / node) ------
__global__ void k0_root(const float* __restrict__ x, const float* __restrict__ rw,
                        const float* __restrict__ nb, const float* __restrict__ b3) {
    int gid = blockIdx.x * blockDim.x + threadIdx.x;
    if (gid >= NN * 4) return;
    int n = gid >> 2, ob = (gid & 3) * 4;
    float xr[16];
#pragma unroll
    for (int i = 0; i < 16; i += 4) {
        float4 v = __ldg((const float4*)&x[(size_t)n * 16 + i]);
        xr[i] = v.x; xr[i + 1] = v.y; xr[i + 2] = v.z; xr[i + 3] = v.w;
    }
    float av[4], bv[4];
#pragma unroll
    for (int oo = 0; oo < 4; oo++) {
        int o = ob + oo;
        float a = __ldg(&nb[o]);
        float b = 0.f;
#pragma unroll
        for (int i = 0; i < 16; i++) {
            a = fmaf(xr[i], __ldg(&rw[i * 16 + o]), a);
            b = fmaf(xr[i], __ldg(&b3[i * 16 + o]), b);
        }
        av[oo] = a; bv[oo] = b;
    }
    *(float4*)&d_agg[(size_t)n * 16 + ob] = make_float4(av[0], av[1], av[2], av[3]);
    *(float4*)&d_b3t[(size_t)n * 16 + ob] = make_float4(bv[0], bv[1], bv[2], bv[3]);
    *(float4*)&d_gout[(size_t)n * 16 + ob] = make_float4(0.f, 0.f, 0.f, 0.f);
    if ((gid & 3) == 0) d_z[n] = 0.f;
}

// ---------------- K2: fused edge pipeline, 2 row-tiles per warp ----------------
__global__ void __launch_bounds__(256, 2)
k2_edge(const float* __restrict__ x, const int* __restrict__ ei,
        const float* __restrict__ ea) {
    extern __shared__ unsigned char smc[];
    int tid = threadIdx.x;
    {
        const uint4* src = (const uint4*)d_wimg;
        uint4* dst = (uint4*)smc;
        for (int i = tid; i < 6288; i += 256) dst[i] = src[i];
    }
    __syncthreads();

    const int w = tid >> 5, lane = tid & 31;
    const int q = lane & 3, l4 = lane >> 2;
    const int bq = 2 * q;
    const float* sw1 = (const float*)(smc + SM_W1P);
    const float* sb2 = (const float*)(smc + SM_B2B);

    for (int tile = blockIdx.x; tile < NT256; tile += gridDim.x) {
        const int base = (tile << 8) + (w << 5) + l4;   // rows base+{0,8,16,24}
        int srcv[4], dstv[4];
        float eav[4][3];
#pragma unroll
        for (int r = 0; r < 4; r++) {
            int e = base + 8 * r;
            srcv[r] = __ldg(&ei[e]);
            dstv[r] = __ldg(&ei[NE + e]);
            eav[r][0] = __ldg(&ea[(size_t)e * 3]);
            eav[r][1] = __ldg(&ea[(size_t)e * 3 + 1]);
            eav[r][2] = __ldg(&ea[(size_t)e * 3 + 2]);
        }

        // ---- L2 (fused L1): C2[m][16,64] for two m16 row-tiles ----
        float C2[2][8][4];
#pragma unroll
        for (int m = 0; m < 2; m++)
#pragma unroll
            for (int nt = 0; nt < 8; nt++)
#pragma unroll
                for (int v = 0; v < 4; v++) C2[m][nt][v] = 0.f;

#pragma unroll
        for (int s = 0; s < 8; s++) {
            float h[4][4];
#pragma unroll
            for (int j = 0; j < 4; j++) {
                float4 wf = *(const float4*)&sw1[(((s * 4 + q) * 4) + j) * 4];
#pragma unroll
                for (int r = 0; r < 4; r++)
                    h[r][j] = fmaxf(fmaf(eav[r][2], wf.z,
                               fmaf(eav[r][1], wf.y, fmaf(eav[r][0], wf.x, wf.w))), 0.f);
            }
            unsigned Ah[2][4];
#pragma unroll
            for (int m = 0; m < 2; m++) {
                Ah[m][0] = packh(h[2 * m][0], h[2 * m][1]);
                Ah[m][1] = packh(h[2 * m + 1][0], h[2 * m + 1][1]);
                Ah[m][2] = packh(h[2 * m][2], h[2 * m][3]);
                Ah[m][3] = packh(h[2 * m + 1][2], h[2 * m + 1][3]);
            }
#pragma unroll
            for (int nt = 0; nt < 8; nt++) {
                uint4 B = *(const uint4*)(smc + SM_B2P + (((s * 8 + nt) * 32 + lane) << 4));
#pragma unroll
                for (int m = 0; m < 2; m++) {
                    mma16816(C2[m][nt], Ah[m], B.x, B.y);
                    mma16816(C2[m][nt], Ah[m], B.z, B.w);
                }
            }
        }

        // ---- epilogue: +b2, relu -> A3 fragments ----
        unsigned A3h[2][4][4];
#pragma unroll
        for (int m = 0; m < 2; m++)
#pragma unroll
            for (int s3 = 0; s3 < 4; s3++) {
                int c = 16 * s3 + bq;
                float2 bA = *(const float2*)&sb2[c];
                float2 bB = *(const float2*)&sb2[c + 8];
                float v00 = fmaxf(C2[m][2 * s3][0] + bA.x, 0.f);
                float v01 = fmaxf(C2[m][2 * s3][1] + bA.y, 0.f);
                float v10 = fmaxf(C2[m][2 * s3][2] + bA.x, 0.f);
                float v11 = fmaxf(C2[m][2 * s3][3] + bA.y, 0.f);
                float v20 = fmaxf(C2[m][2 * s3 + 1][0] + bB.x, 0.f);
                float v21 = fmaxf(C2[m][2 * s3 + 1][1] + bB.y, 0.f);
                float v30 = fmaxf(C2[m][2 * s3 + 1][2] + bB.x, 0.f);
                float v31 = fmaxf(C2[m][2 * s3 + 1][3] + bB.y, 0.f);
                A3h[m][s3][0] = packh(v00, v01);
                A3h[m][s3][1] = packh(v10, v11);
                A3h[m][s3][2] = packh(v20, v21);
                A3h[m][s3][3] = packh(v30, v31);
            }

        // x[src] quarters (loaded after L2 to limit register pressure)
        float4 xq[4];
#pragma unroll
        for (int r = 0; r < 4; r++)
            xq[r] = *(const float4*)&x[(size_t)srcv[r] * 16 + 4 * q];

        // ---- L3 + einsum (weight-hi only: LDS.64 + 1 HMMA per (s3,nt,m)) ----
        float macc[2][2][4];
#pragma unroll
        for (int m = 0; m < 2; m++)
#pragma unroll
            for (int r2 = 0; r2 < 2; r2++)
#pragma unroll
                for (int jj = 0; jj < 4; jj++) macc[m][r2][jj] = 0.f;

#pragma unroll
        for (int grp = 0; grp < 8; grp++) {
            float C3[2][4][4];
#pragma unroll
            for (int m = 0; m < 2; m++)
#pragma unroll
                for (int t = 0; t < 4; t++)
#pragma unroll
                    for (int v = 0; v < 4; v++) C3[m][t][v] = 0.f;
#pragma unroll
            for (int s3 = 0; s3 < 4; s3++) {
#pragma unroll
                for (int t = 0; t < 4; t++) {
                    int nt = grp * 4 + t;
                    uint2 B = *(const uint2*)(smc + SM_B3P + (((s3 * 32 + nt) * 32 + lane) << 4));
#pragma unroll
                    for (int m = 0; m < 2; m++)
                        mma16816(C3[m][t], A3h[m][s3], B.x, B.y);
                }
            }
#pragma unroll
            for (int t = 0; t < 4; t++) {
                const int nt = grp * 4 + t;
                const int i = nt >> 1;
                const int sl = (lane & ~3) | (i >> 2);
                float xv[4];
#pragma unroll
                for (int r = 0; r < 4; r++) {
                    float own;
                    switch (i & 3) {
                        case 0: own = xq[r].x; break;
                        case 1: own = xq[r].y; break;
                        case 2: own = xq[r].z; break;
                        default: own = xq[r].w; break;
                    }
                    xv[r] = __shfl_sync(0xffffffffu, own, sl);
                }
                const int p = nt & 1;
#pragma unroll
                for (int m = 0; m < 2; m++) {
                    macc[m][0][2 * p]     = fmaf(C3[m][t][0], xv[2 * m], macc[m][0][2 * p]);
                    macc[m][0][2 * p + 1] = fmaf(C3[m][t][1], xv[2 * m], macc[m][0][2 * p + 1]);
                    macc[m][1][2 * p]     = fmaf(C3[m][t][2], xv[2 * m + 1], macc[m][1][2 * p]);
                    macc[m][1][2 * p + 1] = fmaf(C3[m][t][3], xv[2 * m + 1], macc[m][1][2 * p + 1]);
                }
            }
        }

        // ---- flush: + b3t[src], vector-red into d_agg[dst] ----
#pragma unroll
        for (int m = 0; m < 2; m++)
#pragma unroll
            for (int r2 = 0; r2 < 2; r2++) {
                int r = 2 * m + r2;
                float2 pA = *(const float2*)&d_b3t[(size_t)srcv[r] * 16 + bq];
                float2 pB = *(const float2*)&d_b3t[(size_t)srcv[r] * 16 + bq + 8];
                float* a = &d_agg[(size_t)dstv[r] * 16];
                redv2(a + bq,     macc[m][r2][0] + pA.x, macc[m][r2][1] + pA.y);
                redv2(a + bq + 8, macc[m][r2][2] + pB.x, macc[m][r2][3] + pB.y);
            }
    }
}

// ---------------- K3: x1 = relu(agg); xt = x1@gat_w (4 threads / node) ---------
__global__ void k3_node(const float* __restrict__ gw, const float* __restrict__ as_,
                        const float* __restrict__ ad_) {
    __shared__ float sw[256], sa[16], sbv[16];
    int tid = threadIdx.x;
    if (tid < 256) sw[tid] = gw[tid];
    if (tid < 16) { sa[tid] = as_[tid]; sbv[tid] = ad_[tid]; }
    __syncthreads();
    int gid = blockIdx.x * blockDim.x + tid;
    if (gid >= NN * 4) return;
    int n = gid >> 2, ob = (gid & 3) * 4;
    float x1[16];
#pragma unroll
    for (int i = 0; i < 16; i++) x1[i] = fmaxf(d_agg[n * 16 + i], 0.f);
    float asrc = 0.f, adst = 0.f;
    float vo[4];
#pragma unroll
    for (int oo = 0; oo < 4; oo++) {
        int o = ob + oo;
        float v = 0.f;
#pragma unroll
        for (int i = 0; i < 16; i++) v = fmaf(x1[i], sw[i * 16 + o], v);
        vo[oo] = v;
        asrc = fmaf(v, sa[o], asrc);
        adst = fmaf(v, sbv[o], adst);
    }
    *(float4*)&d_xt[(size_t)n * 16 + ob] = make_float4(vo[0], vo[1], vo[2], vo[3]);
    asrc += __shfl_xor_sync(0xffffffffu, asrc, 1);
    adst += __shfl_xor_sync(0xffffffffu, adst, 1);
    asrc += __shfl_xor_sync(0xffffffffu, asrc, 2);
    adst += __shfl_xor_sync(0xffffffffu, adst, 2);
    if ((gid & 3) == 0) {
        d_asrc[n] = asrc;
        d_adst[n] = adst;
        d_menc[n] = enc_f(lrelu(asrc + adst));   // self-loop seeds the max
    }
}

// ---------------- K4: edge logits + segment max --------------------------------
__global__ void k4_edge(const int* __restrict__ ei) {
    int e = blockIdx.x * blockDim.x + threadIdx.x;
    if (e >= NE) return;
    int s = ei[e], d = ei[NE + e];
    float v = lrelu(d_asrc[s] + d_adst[d]);
    d_ebuf[e] = v;
    atomicMax(&d_menc[d], enc_f(v));
}

// ---------------- K6: softmax-weighted scatter (4 threads / edge, red.v4) ------
__global__ void k6_edge(const int* __restrict__ ei) {
    int gid = blockIdx.x * blockDim.x + threadIdx.x;
    if (gid >= NE * 4) return;
    int e = gid >> 2, part = gid & 3;
    int s = ei[e], d = ei[NE + e];
    float wv = __expf(d_ebuf[e] - dec_f(d_menc[d]));
    float4 xv = *(const float4*)&d_xt[(size_t)s * 16 + part * 4];
    redv4(&d_gout[(size_t)d * 16 + part * 4],
          wv * xv.x, wv * xv.y, wv * xv.z, wv * xv.w);
    if (part == 0) atomicAdd(&d_z[d], wv);
}

// ---------------- K7: self-loop fold + normalize + fc1 (4 thr / node) ----------
__global__ void k7_node(const float* __restrict__ fw, const float* __restrict__ fb,
                        const float* __restrict__ gb, float* __restrict__ out) {
    __shared__ float sw[1024], sbv[64], sgb[16];
    int tid = threadIdx.x;
    for (int i = tid; i < 1024; i += blockDim.x) sw[i] = fw[i];
    if (tid < 64) sbv[tid] = fb[tid];
    if (tid < 16) sgb[tid] = gb[tid];
    __syncthreads();
    int gid = blockIdx.x * blockDim.x + tid;
    if (gid >= NN * 4) return;
    int n = gid >> 2, jb = (gid & 3) * 16;
    float m = dec_f(d_menc[n]);
    float wself = __expf(lrelu(d_asrc[n] + d_adst[n]) - m);
    float inv = 1.f / (d_z[n] + wself);
    float x2[16];
#pragma unroll
    for (int i = 0; i < 16; i++) {
        float g = d_gout[n * 16 + i] + wself * d_xt[n * 16 + i];
        x2[i] = fmaxf(g * inv + sgb[i], 0.f);
    }
#pragma unroll 4
    for (int jj = 0; jj < 16; jj++) {
        int j = jb + jj;
        float a = sbv[j];
#pragma unroll
        for (int i = 0; i < 16; i++) a = fmaf(x2[i], sw[i * 64 + j], a);
        out[(size_t)n * 64 + j] = fmaxf(a, 0.f);
    }
}

// ---------------- launch -------------------------------------------------------
extern "C" void kernel_launch(void* const* d_in, const int* in_sizes, int n_in,
                              void* d_out, int out_size) {
    const float* x = (const float*)d_in[0];
    const int* ei = (const int*)d_in[1];
    const float* ea = (const float*)d_in[2];
    const float* w1 = (const float*)d_in[4];
    const float* b1 = (const float*)d_in[5];
    const float* w2 = (const float*)d_in[6];
    const float* b2 = (const float*)d_in[7];
    const float* w3 = (const float*)d_in[8];
    const float* b3 = (const float*)d_in[9];
    const float* rootw = (const float*)d_in[10];
    const float* nnb = (const float*)d_in[11];
    const float* gatw = (const float*)d_in[12];
    const float* atts = (const float*)d_in[13];
    const float* attd = (const float*)d_in[14];
    const float* gatb = (const float*)d_in[15];
    const float* fc1w = (const float*)d_in[16];
    const float* fc1b = (const float*)d_in[17];
    float* out = (float*)d_out;

    cudaFuncSetAttribute(k2_edge, cudaFuncAttributeMaxDynamicSharedMemorySize, K2_SMEM);

    k1_prep<<<(25152 + 255) / 256, 256>>>(w1, b1, w2, w3, b2);
    k0_root<<<(NN * 4 + 255) / 256, 256>>>(x, rootw, nnb, b3);
    k2_edge<<<296, 256, K2_SMEM>>>(x, ei, ea);
    k3_node<<<(NN * 4 + 255) / 256, 256>>>(gatw, atts, attd);
    k4_edge<<<(NE + 255) / 256, 256>>>(ei);
    k6_edge<<<(NE * 4 + 255) / 256, 256>>>(ei);
    k7_node<<<(NN * 4 + 255) / 256, 256>>>(fc1w, fc1b, gatb, out);
}

// round 9
// speedup vs baseline: 5.7246x; 1.0779x over previous
#include <cuda_runtime.h>
#include <cuda_fp16.h>
#include <cstdint>

#define NN 50000
#define NE 800000
#define NT256 3125            // 256-edge tiles

// ---------------- device scratch ----------------------------------------------
__device__ float d_agg[NN * 16];
__device__ float d_b3t[NN * 16];
__device__ float d_xt[NN * 16];
__device__ float d_asrc[NN];
__device__ float d_adst[NN];
__device__ unsigned int d_menc[NN];
__device__ float d_z[NN];
__device__ float d_gout[NN * 16];
__device__ float d_ebuf[NE];
// packed weight images: B2P (8192 u32) | B3P (16384 u32) | w1P (512 f32) | b2 (64 f32)
__device__ unsigned d_wimg[25152];

// ---------------- helpers ------------------------------------------------------
__device__ __forceinline__ unsigned enc_f(float f) {
    unsigned u = __float_as_uint(f);
    return (u & 0x80000000u) ? ~u : (u | 0x80000000u);
}
__device__ __forceinline__ float dec_f(unsigned k) {
    return __uint_as_float((k & 0x80000000u) ? (k & 0x7fffffffu) : ~k);
}
__device__ __forceinline__ float lrelu(float v) { return v > 0.f ? v : 0.2f * v; }

__device__ __forceinline__ unsigned packh(float a, float b) {
    unsigned r;
    asm("cvt.rn.f16x2.f32 %0, %1, %2;" : "=r"(r) : "f"(b), "f"(a));
    return r;
}
__device__ __forceinline__ unsigned loh(unsigned hi, float a, float b) {
    float ha = __half2float(__ushort_as_half((unsigned short)(hi & 0xFFFFu)));
    float hb = __half2float(__ushort_as_half((unsigned short)(hi >> 16)));
    return packh(a - ha, b - hb);
}

__device__ __forceinline__ void mma16816(float* c, const unsigned* a,
                                         unsigned b0, unsigned b1) {
    asm volatile(
        "mma.sync.aligned.m16n8k16.row.col.f32.f16.f16.f32 "
        "{%0,%1,%2,%3}, {%4,%5,%6,%7}, {%8,%9}, {%0,%1,%2,%3};"
        : "+f"(c[0]), "+f"(c[1]), "+f"(c[2]), "+f"(c[3])
        : "r"(a[0]), "r"(a[1]), "r"(a[2]), "r"(a[3]), "r"(b0), "r"(b1));
}

// vector global reductions (sm_90+ baseline)
__device__ __forceinline__ void redv2(float* p, float a, float b) {
    asm volatile("red.global.add.v2.f32 [%0], {%1, %2};"
                 :: "l"(p), "f"(a), "f"(b) : "memory");
}
__device__ __forceinline__ void redv4(float* p, float a, float b, float c, float d) {
    asm volatile("red.global.add.v4.f32 [%0], {%1, %2, %3, %4};"
                 :: "l"(p), "f"(a), "f"(b), "f"(c), "f"(d) : "memory");
}

// smem byte offsets inside k2
#define SM_B2P 0
#define SM_B3P 32768
#define SM_W1P 98304
#define SM_B2B 100352
#define K2_SMEM 100608

// ---------------- K1: pack weights into fragment-order hi/lo fp16 images -------
__global__ void k1_prep(const float* __restrict__ w1, const float* __restrict__ b1,
                        const float* __restrict__ w2, const float* __restrict__ w3,
                        const float* __restrict__ b2) {
    int t = blockIdx.x * blockDim.x + threadIdx.x;
    if (t >= 25152) return;
    if (t < 8192) {               // B2P from W2 [128,64]
        int j = t & 3, lane = (t >> 2) & 31, nt = (t >> 7) & 7, s = t >> 10;
        int kk = 16 * s + 2 * (lane & 3) + ((j & 1) ? 8 : 0);
        int n = 8 * nt + (lane >> 2);
        float va = w2[kk * 64 + n], vb = w2[(kk + 1) * 64 + n];
        unsigned hi = packh(va, vb);
        d_wimg[t] = (j < 2) ? hi : loh(hi, va, vb);
    } else if (t < 24576) {       // B3P from W3 [64,256]
        int u = t - 8192;
        int j = u & 3, lane = (u >> 2) & 31, nt = (u >> 7) & 31, s3 = u >> 12;
        int kk = 16 * s3 + 2 * (lane & 3) + ((j & 1) ? 8 : 0);
        int n = 8 * nt + (lane >> 2);
        float va = w3[kk * 256 + n], vb = w3[(kk + 1) * 256 + n];
        unsigned hi = packh(va, vb);
        d_wimg[t] = (j < 2) ? hi : loh(hi, va, vb);
    } else if (t < 25088) {       // w1P: [s][q][j][4] = {w1[0,c],w1[1,c],w1[2,c],b1[c]}
        int f = t - 24576;
        int comp = f & 3, j = (f >> 2) & 3, q = (f >> 4) & 3, s = f >> 6;
        int c = 16 * s + 2 * q + (j & 1) + (j >> 1) * 8;
        float v = (comp < 3) ? w1[comp * 128 + c] : b1[c];
        d_wimg[t] = __float_as_uint(v);
    } else {                      // b2
        d_wimg[t] = __float_as_uint(b2[t - 25088]);
    }
}

// ---------------- K0: agg init + b3 term + zero gout/z (4 threads / node) ------
__global__ void k0_root(const float* __restrict__ x, const float* __restrict__ rw,
                        const float* __restrict__ nb, const float* __restrict__ b3) {
    int gid = blockIdx.x * blockDim.x + threadIdx.x;
    if (gid >= NN * 4) return;
    int n = gid >> 2, ob = (gid & 3) * 4;
    float xr[16];
#pragma unroll
    for (int i = 0; i < 16; i += 4) {
        float4 v = __ldg((const float4*)&x[(size_t)n * 16 + i]);
        xr[i] = v.x; xr[i + 1] = v.y; xr[i + 2] = v.z; xr[i + 3] = v.w;
    }
    float av[4], bv[4];
#pragma unroll
    for (int oo = 0; oo < 4; oo++) {
        int o = ob + oo;
        float a = __ldg(&nb[o]);
        float b = 0.f;
#pragma unroll
        for (int i = 0; i < 16; i++) {
            a = fmaf(xr[i], __ldg(&rw[i * 16 + o]), a);
            b = fmaf(xr[i], __ldg(&b3[i * 16 + o]), b);
        }
        av[oo] = a; bv[oo] = b;
    }
    *(float4*)&d_agg[(size_t)n * 16 + ob] = make_float4(av[0], av[1], av[2], av[3]);
    *(float4*)&d_b3t[(size_t)n * 16 + ob] = make_float4(bv[0], bv[1], bv[2], bv[3]);
    *(float4*)&d_gout[(size_t)n * 16 + ob] = make_float4(0.f, 0.f, 0.f, 0.f);
    if ((gid & 3) == 0) d_z[n] = 0.f;
}

// ---------------- K2: fused edge pipeline, 2 row-tiles per warp, hi-only -------
__global__ void __launch_bounds__(256, 2)
k2_edge(const float* __restrict__ x, const int* __restrict__ ei,
        const float* __restrict__ ea) {
    extern __shared__ unsigned char smc[];
    int tid = threadIdx.x;
    {
        const uint4* src = (const uint4*)d_wimg;
        uint4* dst = (uint4*)smc;
        for (int i = tid; i < 6288; i += 256) dst[i] = src[i];
    }
    __syncthreads();

    const int w = tid >> 5, lane = tid & 31;
    const int q = lane & 3, l4 = lane >> 2;
    const int bq = 2 * q;
    const float* sw1 = (const float*)(smc + SM_W1P);
    const float* sb2 = (const float*)(smc + SM_B2B);

    for (int tile = blockIdx.x; tile < NT256; tile += gridDim.x) {
        const int base = (tile << 8) + (w << 5) + l4;   // rows base+{0,8,16,24}
        int srcv[4], dstv[4];
        float eav[4][3];
#pragma unroll
        for (int r = 0; r < 4; r++) {
            int e = base + 8 * r;
            srcv[r] = __ldg(&ei[e]);
            dstv[r] = __ldg(&ei[NE + e]);
            eav[r][0] = __ldg(&ea[(size_t)e * 3]);
            eav[r][1] = __ldg(&ea[(size_t)e * 3 + 1]);
            eav[r][2] = __ldg(&ea[(size_t)e * 3 + 2]);
        }

        // ---- L2 (fused L1): C2[m][16,64], weight-hi only ----
        float C2[2][8][4];
#pragma unroll
        for (int m = 0; m < 2; m++)
#pragma unroll
            for (int nt = 0; nt < 8; nt++)
#pragma unroll
                for (int v = 0; v < 4; v++) C2[m][nt][v] = 0.f;

#pragma unroll
        for (int s = 0; s < 8; s++) {
            float h[4][4];
#pragma unroll
            for (int j = 0; j < 4; j++) {
                float4 wf = *(const float4*)&sw1[(((s * 4 + q) * 4) + j) * 4];
#pragma unroll
                for (int r = 0; r < 4; r++)
                    h[r][j] = fmaxf(fmaf(eav[r][2], wf.z,
                               fmaf(eav[r][1], wf.y, fmaf(eav[r][0], wf.x, wf.w))), 0.f);
            }
            unsigned Ah[2][4];
#pragma unroll
            for (int m = 0; m < 2; m++) {
                Ah[m][0] = packh(h[2 * m][0], h[2 * m][1]);
                Ah[m][1] = packh(h[2 * m + 1][0], h[2 * m + 1][1]);
                Ah[m][2] = packh(h[2 * m][2], h[2 * m][3]);
                Ah[m][3] = packh(h[2 * m + 1][2], h[2 * m + 1][3]);
            }
#pragma unroll
            for (int nt = 0; nt < 8; nt++) {
                uint2 B = *(const uint2*)(smc + SM_B2P + (((s * 8 + nt) * 32 + lane) << 4));
#pragma unroll
                for (int m = 0; m < 2; m++)
                    mma16816(C2[m][nt], Ah[m], B.x, B.y);
            }
        }

        // ---- epilogue: +b2, relu -> A3 fragments ----
        unsigned A3h[2][4][4];
#pragma unroll
        for (int m = 0; m < 2; m++)
#pragma unroll
            for (int s3 = 0; s3 < 4; s3++) {
                int c = 16 * s3 + bq;
                float2 bA = *(const float2*)&sb2[c];
                float2 bB = *(const float2*)&sb2[c + 8];
                float v00 = fmaxf(C2[m][2 * s3][0] + bA.x, 0.f);
                float v01 = fmaxf(C2[m][2 * s3][1] + bA.y, 0.f);
                float v10 = fmaxf(C2[m][2 * s3][2] + bA.x, 0.f);
                float v11 = fmaxf(C2[m][2 * s3][3] + bA.y, 0.f);
                float v20 = fmaxf(C2[m][2 * s3 + 1][0] + bB.x, 0.f);
                float v21 = fmaxf(C2[m][2 * s3 + 1][1] + bB.y, 0.f);
                float v30 = fmaxf(C2[m][2 * s3 + 1][2] + bB.x, 0.f);
                float v31 = fmaxf(C2[m][2 * s3 + 1][3] + bB.y, 0.f);
                A3h[m][s3][0] = packh(v00, v01);
                A3h[m][s3][1] = packh(v10, v11);
                A3h[m][s3][2] = packh(v20, v21);
                A3h[m][s3][3] = packh(v30, v31);
            }

        // x[src] quarters (loaded after L2 to limit register pressure)
        float4 xq[4];
#pragma unroll
        for (int r = 0; r < 4; r++)
            xq[r] = *(const float4*)&x[(size_t)srcv[r] * 16 + 4 * q];

        // ---- L3 + einsum (weight-hi only) ----
        float macc[2][2][4];
#pragma unroll
        for (int m = 0; m < 2; m++)
#pragma unroll
            for (int r2 = 0; r2 < 2; r2++)
#pragma unroll
                for (int jj = 0; jj < 4; jj++) macc[m][r2][jj] = 0.f;

#pragma unroll
        for (int grp = 0; grp < 8; grp++) {
            float C3[2][4][4];
#pragma unroll
            for (int m = 0; m < 2; m++)
#pragma unroll
                for (int t = 0; t < 4; t++)
#pragma unroll
                    for (int v = 0; v < 4; v++) C3[m][t][v] = 0.f;
#pragma unroll
            for (int s3 = 0; s3 < 4; s3++) {
#pragma unroll
                for (int t = 0; t < 4; t++) {
                    int nt = grp * 4 + t;
                    uint2 B = *(const uint2*)(smc + SM_B3P + (((s3 * 32 + nt) * 32 + lane) << 4));
#pragma unroll
                    for (int m = 0; m < 2; m++)
                        mma16816(C3[m][t], A3h[m][s3], B.x, B.y);
                }
            }
#pragma unroll
            for (int t = 0; t < 4; t++) {
                const int nt = grp * 4 + t;
                const int i = nt >> 1;
                const int sl = (lane & ~3) | (i >> 2);
                float xv[4];
#pragma unroll
                for (int r = 0; r < 4; r++) {
                    float own;
                    switch (i & 3) {
                        case 0: own = xq[r].x; break;
                        case 1: own = xq[r].y; break;
                        case 2: own = xq[r].z; break;
                        default: own = xq[r].w; break;
                    }
                    xv[r] = __shfl_sync(0xffffffffu, own, sl);
                }
                const int p = nt & 1;
#pragma unroll
                for (int m = 0; m < 2; m++) {
                    macc[m][0][2 * p]     = fmaf(C3[m][t][0], xv[2 * m], macc[m][0][2 * p]);
                    macc[m][0][2 * p + 1] = fmaf(C3[m][t][1], xv[2 * m], macc[m][0][2 * p + 1]);
                    macc[m][1][2 * p]     = fmaf(C3[m][t][2], xv[2 * m + 1], macc[m][1][2 * p]);
                    macc[m][1][2 * p + 1] = fmaf(C3[m][t][3], xv[2 * m + 1], macc[m][1][2 * p + 1]);
                }
            }
        }

        // ---- flush: + b3t[src], vector-red into d_agg[dst] ----
#pragma unroll
        for (int m = 0; m < 2; m++)
#pragma unroll
            for (int r2 = 0; r2 < 2; r2++) {
                int r = 2 * m + r2;
                float2 pA = *(const float2*)&d_b3t[(size_t)srcv[r] * 16 + bq];
                float2 pB = *(const float2*)&d_b3t[(size_t)srcv[r] * 16 + bq + 8];
                float* a = &d_agg[(size_t)dstv[r] * 16];
                redv2(a + bq,     macc[m][r2][0] + pA.x, macc[m][r2][1] + pA.y);
                redv2(a + bq + 8, macc[m][r2][2] + pB.x, macc[m][r2][3] + pB.y);
            }
    }
}

// ---------------- K3: x1 = relu(agg); xt = x1@gat_w (4 threads / node) ---------
__global__ void k3_node(const float* __restrict__ gw, const float* __restrict__ as_,
                        const float* __restrict__ ad_) {
    __shared__ float sw[256], sa[16], sbv[16];
    int tid = threadIdx.x;
    if (tid < 256) sw[tid] = gw[tid];
    if (tid < 16) { sa[tid] = as_[tid]; sbv[tid] = ad_[tid]; }
    __syncthreads();
    int gid = blockIdx.x * blockDim.x + tid;
    if (gid >= NN * 4) return;
    int n = gid >> 2, ob = (gid & 3) * 4;
    float x1[16];
#pragma unroll
    for (int i = 0; i < 16; i++) x1[i] = fmaxf(d_agg[n * 16 + i], 0.f);
    float asrc = 0.f, adst = 0.f;
    float vo[4];
#pragma unroll
    for (int oo = 0; oo < 4; oo++) {
        int o = ob + oo;
        float v = 0.f;
#pragma unroll
        for (int i = 0; i < 16; i++) v = fmaf(x1[i], sw[i * 16 + o], v);
        vo[oo] = v;
        asrc = fmaf(v, sa[o], asrc);
        adst = fmaf(v, sbv[o], adst);
    }
    *(float4*)&d_xt[(size_t)n * 16 + ob] = make_float4(vo[0], vo[1], vo[2], vo[3]);
    asrc += __shfl_xor_sync(0xffffffffu, asrc, 1);
    adst += __shfl_xor_sync(0xffffffffu, adst, 1);
    asrc += __shfl_xor_sync(0xffffffffu, asrc, 2);
    adst += __shfl_xor_sync(0xffffffffu, adst, 2);
    if ((gid & 3) == 0) {
        d_asrc[n] = asrc;
        d_adst[n] = adst;
        d_menc[n] = enc_f(lrelu(asrc + adst));   // self-loop seeds the max
    }
}

// ---------------- K4: edge logits + segment max --------------------------------
__global__ void k4_edge(const int* __restrict__ ei) {
    int e = blockIdx.x * blockDim.x + threadIdx.x;
    if (e >= NE) return;
    int s = ei[e], d = ei[NE + e];
    float v = lrelu(d_asrc[s] + d_adst[d]);
    d_ebuf[e] = v;
    atomicMax(&d_menc[d], enc_f(v));
}

// ---------------- K6: softmax-weighted scatter (4 threads / edge, red.v4) ------
__global__ void k6_edge(const int* __restrict__ ei) {
    int gid = blockIdx.x * blockDim.x + threadIdx.x;
    if (gid >= NE * 4) return;
    int e = gid >> 2, part = gid & 3;
    int s = ei[e], d = ei[NE + e];
    float wv = __expf(d_ebuf[e] - dec_f(d_menc[d]));
    float4 xv = *(const float4*)&d_xt[(size_t)s * 16 + part * 4];
    redv4(&d_gout[(size_t)d * 16 + part * 4],
          wv * xv.x, wv * xv.y, wv * xv.z, wv * xv.w);
    if (part == 0) atomicAdd(&d_z[d], wv);
}

// ---------------- K7: self-loop fold + normalize + fc1 (4 thr / node) ----------
__global__ void k7_node(const float* __restrict__ fw, const float* __restrict__ fb,
                        const float* __restrict__ gb, float* __restrict__ out) {
    __shared__ float sw[1024], sbv[64], sgb[16];
    int tid = threadIdx.x;
    for (int i = tid; i < 1024; i += blockDim.x) sw[i] = fw[i];
    if (tid < 64) sbv[tid] = fb[tid];
    if (tid < 16) sgb[tid] = gb[tid];
    __syncthreads();
    int gid = blockIdx.x * blockDim.x + tid;
    if (gid >= NN * 4) return;
    int n = gid >> 2, jb = (gid & 3) * 16;
    float m = dec_f(d_menc[n]);
    float wself = __expf(lrelu(d_asrc[n] + d_adst[n]) - m);
    float inv = 1.f / (d_z[n] + wself);
    float x2[16];
#pragma unroll
    for (int i = 0; i < 16; i++) {
        float g = d_gout[n * 16 + i] + wself * d_xt[n * 16 + i];
        x2[i] = fmaxf(g * inv + sgb[i], 0.f);
    }
#pragma unroll 4
    for (int jj = 0; jj < 16; jj++) {
        int j = jb + jj;
        float a = sbv[j];
#pragma unroll
        for (int i = 0; i < 16; i++) a = fmaf(x2[i], sw[i * 64 + j], a);
        out[(size_t)n * 64 + j] = fmaxf(a, 0.f);
    }
}

// ---------------- launch -------------------------------------------------------
extern "C" void kernel_launch(void* const* d_in, const int* in_sizes, int n_in,
                              void* d_out, int out_size) {
    const float* x = (const float*)d_in[0];
    const int* ei = (const int*)d_in[1];
    const float* ea = (const float*)d_in[2];
    const float* w1 = (const float*)d_in[4];
    const float* b1 = (const float*)d_in[5];
    const float* w2 = (const float*)d_in[6];
    const float* b2 = (const float*)d_in[7];
    const float* w3 = (const float*)d_in[8];
    const float* b3 = (const float*)d_in[9];
    const float* rootw = (const float*)d_in[10];
    const float* nnb = (const float*)d_in[11];
    const float* gatw = (const float*)d_in[12];
    const float* atts = (const float*)d_in[13];
    const float* attd = (const float*)d_in[14];
    const float* gatb = (const float*)d_in[15];
    const float* fc1w = (const float*)d_in[16];
    const float* fc1b = (const float*)d_in[17];
    float* out = (float*)d_out;

    cudaFuncSetAttribute(k2_edge, cudaFuncAttributeMaxDynamicSharedMemorySize, K2_SMEM);

    k1_prep<<<(25152 + 255) / 256, 256>>>(w1, b1, w2, w3, b2);
    k0_root<<<(NN * 4 + 255) / 256, 256>>>(x, rootw, nnb, b3);
    k2_edge<<<296, 256, K2_SMEM>>>(x, ei, ea);
    k3_node<<<(NN * 4 + 255) / 256, 256>>>(gatw, atts, attd);
    k4_edge<<<(NE + 255) / 256, 256>>>(ei);
    k6_edge<<<(NE * 4 + 255) / 256, 256>>>(ei);
    k7_node<<<(NN * 4 + 255) / 256, 256>>>(fc1w, fc1b, gatb, out);
}

// round 11
// speedup vs baseline: 6.1699x; 1.0778x over previous
#include <cuda_runtime.h>
#include <cuda_fp16.h>
#include <cstdint>

#define NN 50000
#define NE 800000
#define NT256 3125            // 256-edge tiles

// ---------------- device scratch ----------------------------------------------
__device__ float d_agg[NN * 16];
__device__ float d_b3t[NN * 16];
__device__ float d_xt[NN * 16];
__device__ float d_asrc[NN];
__device__ float d_adst[NN];
__device__ unsigned int d_menc[NN];
__device__ float d_z[NN];
__device__ float d_gout[NN * 16];
__device__ float d_ebuf[NE];
// packed weight images (compact, conflict-free):
// B1F (1024 u32: {hi,lo} uint2/lane) | B2H (4096) | B3H (8192) | b2 (64)
__device__ unsigned d_wimg[13376];

// ---------------- helpers ------------------------------------------------------
__device__ __forceinline__ unsigned enc_f(float f) {
    unsigned u = __float_as_uint(f);
    return (u & 0x80000000u) ? ~u : (u | 0x80000000u);
}
__device__ __forceinline__ float dec_f(unsigned k) {
    return __uint_as_float((k & 0x80000000u) ? (k & 0x7fffffffu) : ~k);
}
__device__ __forceinline__ float lrelu(float v) { return v > 0.f ? v : 0.2f * v; }

__device__ __forceinline__ unsigned packh(float a, float b) {
    unsigned r;
    asm("cvt.rn.f16x2.f32 %0, %1, %2;" : "=r"(r) : "f"(b), "f"(a));
    return r;
}
__device__ __forceinline__ unsigned loh(unsigned hi, float a, float b) {
    float ha = __half2float(__ushort_as_half((unsigned short)(hi & 0xFFFFu)));
    float hb = __half2float(__ushort_as_half((unsigned short)(hi >> 16)));
    return packh(a - ha, b - hb);
}

__device__ __forceinline__ void mma16816(float* c, const unsigned* a,
                                         unsigned b0, unsigned b1) {
    asm volatile(
        "mma.sync.aligned.m16n8k16.row.col.f32.f16.f16.f32 "
        "{%0,%1,%2,%3}, {%4,%5,%6,%7}, {%8,%9}, {%0,%1,%2,%3};"
        : "+f"(c[0]), "+f"(c[1]), "+f"(c[2]), "+f"(c[3])
        : "r"(a[0]), "r"(a[1]), "r"(a[2]), "r"(a[3]), "r"(b0), "r"(b1));
}

// vector global reductions (sm_90+ baseline)
__device__ __forceinline__ void redv2(float* p, float a, float b) {
    asm volatile("red.global.add.v2.f32 [%0], {%1, %2};"
                 :: "l"(p), "f"(a), "f"(b) : "memory");
}
__device__ __forceinline__ void redv4(float* p, float a, float b, float c, float d) {
    asm volatile("red.global.add.v4.f32 [%0], {%1, %2, %3, %4};"
                 :: "l"(p), "f"(a), "f"(b), "f"(c), "f"(d) : "memory");
}

// smem byte offsets inside k2 (all 8B-aligned; lane stride 8B -> conflict-free)
#define SM_B1F 0
#define SM_B2H 4096
#define SM_B3H 20480
#define SM_B2B 53248
#define K2_SMEM 53504

// ---------------- K1: pack weights, compact conflict-free images ---------------
// B1F entry (nt 0..15, lane): uint2 {hi, lo} of the m16n8k16 B fragment for the
//   L1 GEMM with K-rows {w1[0], w1[1], w1[2], b1, 0...}: q=0 -> (w1[0,n],w1[1,n]),
//   q=1 -> (w1[2,n], b1[n]), q>=2 -> 0.  lo goes in the b1 (k8-15) slot; A
//   duplicates ea there, so one HMMA applies W1 exactly.
// B2H/B3H: hi-only {b0h, b1h} uint2 per (step, nt, lane), 8B lane stride.
__global__ void k1_prep(const float* __restrict__ w1, const float* __restrict__ b1,
                        const float* __restrict__ w2, const float* __restrict__ w3,
                        const float* __restrict__ b2) {
    int t = blockIdx.x * blockDim.x + threadIdx.x;
    if (t >= 13376) return;
    if (t < 1024) {               // B1F
        int j = t & 1, e = t >> 1;
        int lane = e & 31, nt = e >> 5;
        int q = lane & 3, n = 8 * nt + (lane >> 2);
        float va = 0.f, vb = 0.f;
        if (q == 0) { va = w1[n]; vb = w1[128 + n]; }
        else if (q == 1) { va = w1[256 + n]; vb = b1[n]; }
        unsigned hi = packh(va, vb);
        d_wimg[t] = (q < 2) ? ((j == 0) ? hi : loh(hi, va, vb)) : 0u;
    } else if (t < 5120) {        // B2H from W2 [128,64]
        int u = t - 1024;
        int j = u & 1, e = u >> 1;
        int lane = e & 31, nt = (e >> 5) & 7, s = e >> 8;
        int kk = 16 * s + 2 * (lane & 3) + (j ? 8 : 0);
        int n = 8 * nt + (lane >> 2);
        d_wimg[t] = packh(w2[kk * 64 + n], w2[(kk + 1) * 64 + n]);
    } else if (t < 13312) {       // B3H from W3 [64,256]
        int u = t - 5120;
        int j = u & 1, e = u >> 1;
        int lane = e & 31, nt = (e >> 5) & 31, s3 = e >> 10;
        int kk = 16 * s3 + 2 * (lane & 3) + (j ? 8 : 0);
        int n = 8 * nt + (lane >> 2);
        d_wimg[t] = packh(w3[kk * 256 + n], w3[(kk + 1) * 256 + n]);
    } else {                      // b2
        d_wimg[t] = __float_as_uint(b2[t - 13312]);
    }
}

// ---------------- K0: agg init + b3 term + zero gout/z (4 threads / node) ------
__global__ void k0_root(const float* __restrict__ x, const float* __restrict__ rw,
                        const float* __restrict__ nb, const float* __restrict__ b3) {
    int gid = blockIdx.x * blockDim.x + threadIdx.x;
    if (gid >= NN * 4) return;
    int n = gid >> 2, ob = (gid & 3) * 4;
    float xr[16];
#pragma unroll
    for (int i = 0; i < 16; i += 4) {
        float4 v = __ldg((const float4*)&x[(size_t)n * 16 + i]);
        xr[i] = v.x; xr[i + 1] = v.y; xr[i + 2] = v.z; xr[i + 3] = v.w;
    }
    float av[4], bv[4];
#pragma unroll
    for (int oo = 0; oo < 4; oo++) {
        int o = ob + oo;
        float a = __ldg(&nb[o]);
        float b = 0.f;
#pragma unroll
        for (int i = 0; i < 16; i++) {
            a = fmaf(xr[i], __ldg(&rw[i * 16 + o]), a);
            b = fmaf(xr[i], __ldg(&b3[i * 16 + o]), b);
        }
        av[oo] = a; bv[oo] = b;
    }
    *(float4*)&d_agg[(size_t)n * 16 + ob] = make_float4(av[0], av[1], av[2], av[3]);
    *(float4*)&d_b3t[(size_t)n * 16 + ob] = make_float4(bv[0], bv[1], bv[2], bv[3]);
    *(float4*)&d_gout[(size_t)n * 16 + ob] = make_float4(0.f, 0.f, 0.f, 0.f);
    if ((gid & 3) == 0) d_z[n] = 0.f;
}

// ---------------- K2: fully tensorized edge pipeline ---------------------------
__global__ void __launch_bounds__(256, 2)
k2_edge(const float* __restrict__ x, const int* __restrict__ ei,
        const float* __restrict__ ea) {
    extern __shared__ unsigned char smc[];
    int tid = threadIdx.x;
    {
        const uint4* src = (const uint4*)d_wimg;
        uint4* dst = (uint4*)smc;
        for (int i = tid; i < 3344; i += 256) dst[i] = src[i];   // 13376 u32 = 3344 uint4
    }
    __syncthreads();

    const int w = tid >> 5, lane = tid & 31;
    const int q = lane & 3, l4 = lane >> 2;
    const int bq = 2 * q;
    const float* sb2 = (const float*)(smc + SM_B2B);

    for (int tile = blockIdx.x; tile < NT256; tile += gridDim.x) {
        const int base = (tile << 8) + (w << 5) + l4;   // rows base+{0,8,16,24}
        int srcv[4], dstv[4];
        unsigned eaf[2][2];                              // L1 A fragments
#pragma unroll
        for (int r = 0; r < 4; r += 2) {
            int e0 = base + 8 * r, e1 = e0 + 8;
            srcv[r] = __ldg(&ei[e0]);     srcv[r + 1] = __ldg(&ei[e1]);
            dstv[r] = __ldg(&ei[NE + e0]); dstv[r + 1] = __ldg(&ei[NE + e1]);
            float a0 = __ldg(&ea[(size_t)e0 * 3]);
            float a1 = __ldg(&ea[(size_t)e0 * 3 + 1]);
            float a2 = __ldg(&ea[(size_t)e0 * 3 + 2]);
            float b0 = __ldg(&ea[(size_t)e1 * 3]);
            float b1v = __ldg(&ea[(size_t)e1 * 3 + 1]);
            float b2v = __ldg(&ea[(size_t)e1 * 3 + 2]);
            int m = r >> 1;
            eaf[m][0] = (q == 0) ? packh(a0, a1) : ((q == 1) ? packh(a2, 1.0f) : 0u);
            eaf[m][1] = (q == 0) ? packh(b0, b1v) : ((q == 1) ? packh(b2v, 1.0f) : 0u);
        }

        // ---- L2 (with L1 on tensor cores): C2[m][16,64] ----
        float C2[2][8][4];
#pragma unroll
        for (int m = 0; m < 2; m++)
#pragma unroll
            for (int nt = 0; nt < 8; nt++)
#pragma unroll
                for (int v = 0; v < 4; v++) C2[m][nt][v] = 0.f;

#pragma unroll
        for (int s = 0; s < 8; s++) {
            // L1: C1 = ea @ W1 + b1 (exact W1 via hi in b0-slot, lo in b1-slot)
            float C1[2][2][4];
#pragma unroll
            for (int ntl = 0; ntl < 2; ntl++)
#pragma unroll
                for (int m = 0; m < 2; m++)
#pragma unroll
                    for (int v = 0; v < 4; v++) C1[ntl][m][v] = 0.f;
#pragma unroll
            for (int ntl = 0; ntl < 2; ntl++) {
                uint2 bw = *(const uint2*)(smc + SM_B1F + (((2 * s + ntl) * 32 + lane) << 3));
#pragma unroll
                for (int m = 0; m < 2; m++) {
                    unsigned a[4] = {eaf[m][0], eaf[m][1], eaf[m][0], eaf[m][1]};
                    mma16816(C1[ntl][m], a, bw.x, bw.y);
                }
            }
            // relu + pack -> L2 A fragments (C1 layout == A fragment layout)
            unsigned Ah[2][4];
#pragma unroll
            for (int m = 0; m < 2; m++) {
                Ah[m][0] = packh(fmaxf(C1[0][m][0], 0.f), fmaxf(C1[0][m][1], 0.f));
                Ah[m][1] = packh(fmaxf(C1[0][m][2], 0.f), fmaxf(C1[0][m][3], 0.f));
                Ah[m][2] = packh(fmaxf(C1[1][m][0], 0.f), fmaxf(C1[1][m][1], 0.f));
                Ah[m][3] = packh(fmaxf(C1[1][m][2], 0.f), fmaxf(C1[1][m][3], 0.f));
            }
#pragma unroll
            for (int nt = 0; nt < 8; nt++) {
                uint2 B = *(const uint2*)(smc + SM_B2H + (((s * 8 + nt) * 32 + lane) << 3));
#pragma unroll
                for (int m = 0; m < 2; m++)
                    mma16816(C2[m][nt], Ah[m], B.x, B.y);
            }
        }

        // ---- epilogue: +b2, relu -> A3 fragments ----
        unsigned A3h[2][4][4];
#pragma unroll
        for (int m = 0; m < 2; m++)
#pragma unroll
            for (int s3 = 0; s3 < 4; s3++) {
                int c = 16 * s3 + bq;
                float2 bA = *(const float2*)&sb2[c];
                float2 bB = *(const float2*)&sb2[c + 8];
                float v00 = fmaxf(C2[m][2 * s3][0] + bA.x, 0.f);
                float v01 = fmaxf(C2[m][2 * s3][1] + bA.y, 0.f);
                float v10 = fmaxf(C2[m][2 * s3][2] + bA.x, 0.f);
                float v11 = fmaxf(C2[m][2 * s3][3] + bA.y, 0.f);
                float v20 = fmaxf(C2[m][2 * s3 + 1][0] + bB.x, 0.f);
                float v21 = fmaxf(C2[m][2 * s3 + 1][1] + bB.y, 0.f);
                float v30 = fmaxf(C2[m][2 * s3 + 1][2] + bB.x, 0.f);
                float v31 = fmaxf(C2[m][2 * s3 + 1][3] + bB.y, 0.f);
                A3h[m][s3][0] = packh(v00, v01);
                A3h[m][s3][1] = packh(v10, v11);
                A3h[m][s3][2] = packh(v20, v21);
                A3h[m][s3][3] = packh(v30, v31);
            }

        // x[src] quarters (loaded after L2 to limit register pressure)
        float4 xq[4];
#pragma unroll
        for (int r = 0; r < 4; r++)
            xq[r] = *(const float4*)&x[(size_t)srcv[r] * 16 + 4 * q];

        // ---- L3 + einsum (weight-hi only) ----
        float macc[2][2][4];
#pragma unroll
        for (int m = 0; m < 2; m++)
#pragma unroll
            for (int r2 = 0; r2 < 2; r2++)
#pragma unroll
                for (int jj = 0; jj < 4; jj++) macc[m][r2][jj] = 0.f;

#pragma unroll
        for (int grp = 0; grp < 8; grp++) {
            float C3[2][4][4];
#pragma unroll
            for (int m = 0; m < 2; m++)
#pragma unroll
                for (int t = 0; t < 4; t++)
#pragma unroll
                    for (int v = 0; v < 4; v++) C3[m][t][v] = 0.f;
#pragma unroll
            for (int s3 = 0; s3 < 4; s3++) {
#pragma unroll
                for (int t = 0; t < 4; t++) {
                    int nt = grp * 4 + t;
                    uint2 B = *(const uint2*)(smc + SM_B3H + (((s3 * 32 + nt) * 32 + lane) << 3));
#pragma unroll
                    for (int m = 0; m < 2; m++)
                        mma16816(C3[m][t], A3h[m][s3], B.x, B.y);
                }
            }
#pragma unroll
            for (int t = 0; t < 4; t++) {
                const int nt = grp * 4 + t;
                const int i = nt >> 1;
                const int sl = (lane & ~3) | (i >> 2);
                float xv[4];
#pragma unroll
                for (int r = 0; r < 4; r++) {
                    float own;
                    switch (i & 3) {
                        case 0: own = xq[r].x; break;
                        case 1: own = xq[r].y; break;
                        case 2: own = xq[r].z; break;
                        default: own = xq[r].w; break;
                    }
                    xv[r] = __shfl_sync(0xffffffffu, own, sl);
                }
                const int p = nt & 1;
#pragma unroll
                for (int m = 0; m < 2; m++) {
                    macc[m][0][2 * p]     = fmaf(C3[m][t][0], xv[2 * m], macc[m][0][2 * p]);
                    macc[m][0][2 * p + 1] = fmaf(C3[m][t][1], xv[2 * m], macc[m][0][2 * p + 1]);
                    macc[m][1][2 * p]     = fmaf(C3[m][t][2], xv[2 * m + 1], macc[m][1][2 * p]);
                    macc[m][1][2 * p + 1] = fmaf(C3[m][t][3], xv[2 * m + 1], macc[m][1][2 * p + 1]);
                }
            }
        }

        // ---- flush: + b3t[src], vector-red into d_agg[dst] ----
#pragma unroll
        for (int m = 0; m < 2; m++)
#pragma unroll
            for (int r2 = 0; r2 < 2; r2++) {
                int r = 2 * m + r2;
                float2 pA = *(const float2*)&d_b3t[(size_t)srcv[r] * 16 + bq];
                float2 pB = *(const float2*)&d_b3t[(size_t)srcv[r] * 16 + bq + 8];
                float* a = &d_agg[(size_t)dstv[r] * 16];
                redv2(a + bq,     macc[m][r2][0] + pA.x, macc[m][r2][1] + pA.y);
                redv2(a + bq + 8, macc[m][r2][2] + pB.x, macc[m][r2][3] + pB.y);
            }
    }
}

// ---------------- K3: x1 = relu(agg); xt = x1@gat_w (4 threads / node) ---------
__global__ void k3_node(const float* __restrict__ gw, const float* __restrict__ as_,
                        const float* __restrict__ ad_) {
    __shared__ float sw[256], sa[16], sbv[16];
    int tid = threadIdx.x;
    if (tid < 256) sw[tid] = gw[tid];
    if (tid < 16) { sa[tid] = as_[tid]; sbv[tid] = ad_[tid]; }
    __syncthreads();
    int gid = blockIdx.x * blockDim.x + tid;
    if (gid >= NN * 4) return;
    int n = gid >> 2, ob = (gid & 3) * 4;
    float x1[16];
#pragma unroll
    for (int i = 0; i < 16; i++) x1[i] = fmaxf(d_agg[n * 16 + i], 0.f);
    float asrc = 0.f, adst = 0.f;
    float vo[4];
#pragma unroll
    for (int oo = 0; oo < 4; oo++) {
        int o = ob + oo;
        float v = 0.f;
#pragma unroll
        for (int i = 0; i < 16; i++) v = fmaf(x1[i], sw[i * 16 + o], v);
        vo[oo] = v;
        asrc = fmaf(v, sa[o], asrc);
        adst = fmaf(v, sbv[o], adst);
    }
    *(float4*)&d_xt[(size_t)n * 16 + ob] = make_float4(vo[0], vo[1], vo[2], vo[3]);
    asrc += __shfl_xor_sync(0xffffffffu, asrc, 1);
    adst += __shfl_xor_sync(0xffffffffu, adst, 1);
    asrc += __shfl_xor_sync(0xffffffffu, asrc, 2);
    adst += __shfl_xor_sync(0xffffffffu, adst, 2);
    if ((gid & 3) == 0) {
        d_asrc[n] = asrc;
        d_adst[n] = adst;
        d_menc[n] = enc_f(lrelu(asrc + adst));   // self-loop seeds the max
    }
}

// ---------------- K4: edge logits + segment max --------------------------------
__global__ void k4_edge(const int* __restrict__ ei) {
    int e = blockIdx.x * blockDim.x + threadIdx.x;
    if (e >= NE) return;
    int s = ei[e], d = ei[NE + e];
    float v = lrelu(d_asrc[s] + d_adst[d]);
    d_ebuf[e] = v;
    atomicMax(&d_menc[d], enc_f(v));
}

// ---------------- K6: softmax-weighted scatter (4 threads / edge, red.v4) ------
__global__ void k6_edge(const int* __restrict__ ei) {
    int gid = blockIdx.x * blockDim.x + threadIdx.x;
    if (gid >= NE * 4) return;
    int e = gid >> 2, part = gid & 3;
    int s = ei[e], d = ei[NE + e];
    float wv = __expf(d_ebuf[e] - dec_f(d_menc[d]));
    float4 xv = *(const float4*)&d_xt[(size_t)s * 16 + part * 4];
    redv4(&d_gout[(size_t)d * 16 + part * 4],
          wv * xv.x, wv * xv.y, wv * xv.z, wv * xv.w);
    if (part == 0) atomicAdd(&d_z[d], wv);
}

// ---------------- K7: self-loop fold + normalize + fc1 (4 thr / node) ----------
__global__ void k7_node(const float* __restrict__ fw, const float* __restrict__ fb,
                        const float* __restrict__ gb, float* __restrict__ out) {
    __shared__ float sw[1024], sbv[64], sgb[16];
    int tid = threadIdx.x;
    for (int i = tid; i < 1024; i += blockDim.x) sw[i] = fw[i];
    if (tid < 64) sbv[tid] = fb[tid];
    if (tid < 16) sgb[tid] = gb[tid];
    __syncthreads();
    int gid = blockIdx.x * blockDim.x + tid;
    if (gid >= NN * 4) return;
    int n = gid >> 2, jb = (gid & 3) * 16;
    float m = dec_f(d_menc[n]);
    float wself = __expf(lrelu(d_asrc[n] + d_adst[n]) - m);
    float inv = 1.f / (d_z[n] + wself);
    float x2[16];
#pragma unroll
    for (int i = 0; i < 16; i++) {
        float g = d_gout[n * 16 + i] + wself * d_xt[n * 16 + i];
        x2[i] = fmaxf(g * inv + sgb[i], 0.f);
    }
#pragma unroll 4
    for (int jj = 0; jj < 16; jj++) {
        int j = jb + jj;
        float a = sbv[j];
#pragma unroll
        for (int i = 0; i < 16; i++) a = fmaf(x2[i], sw[i * 64 + j], a);
        out[(size_t)n * 64 + j] = fmaxf(a, 0.f);
    }
}

// ---------------- launch -------------------------------------------------------
extern "C" void kernel_launch(void* const* d_in, const int* in_sizes, int n_in,
                              void* d_out, int out_size) {
    const float* x = (const float*)d_in[0];
    const int* ei = (const int*)d_in[1];
    const float* ea = (const float*)d_in[2];
    const float* w1 = (const float*)d_in[4];
    const float* b1 = (const float*)d_in[5];
    const float* w2 = (const float*)d_in[6];
    const float* b2 = (const float*)d_in[7];
    const float* w3 = (const float*)d_in[8];
    const float* b3 = (const float*)d_in[9];
    const float* rootw = (const float*)d_in[10];
    const float* nnb = (const float*)d_in[11];
    const float* gatw = (const float*)d_in[12];
    const float* atts = (const float*)d_in[13];
    const float* attd = (const float*)d_in[14];
    const float* gatb = (const float*)d_in[15];
    const float* fc1w = (const float*)d_in[16];
    const float* fc1b = (const float*)d_in[17];
    float* out = (float*)d_out;

    cudaFuncSetAttribute(k2_edge, cudaFuncAttributeMaxDynamicSharedMemorySize, K2_SMEM);

    k1_prep<<<(13376 + 255) / 256, 256>>>(w1, b1, w2, w3, b2);
    k0_root<<<(NN * 4 + 255) / 256, 256>>>(x, rootw, nnb, b3);
    k2_edge<<<296, 256, K2_SMEM>>>(x, ei, ea);
    k3_node<<<(NN * 4 + 255) / 256, 256>>>(gatw, atts, attd);
    k4_edge<<<(NE + 255) / 256, 256>>>(ei);
    k6_edge<<<(NE * 4 + 255) / 256, 256>>>(ei);
    k7_node<<<(NN * 4 + 255) / 256, 256>>>(fc1w, fc1b, gatb, out);
}